// round 8
// baseline (speedup 1.0000x reference)
#include <cuda_runtime.h>
#include <cstdint>
#include <cstdio>

// ---------------- problem constants ----------------
constexpr int NN  = 50000;   // nodes
constexpr int NE  = 800000;  // edges
constexpr int DD  = 128;     // channels
constexpr int NH  = 8;       // heads
constexpr int EDD = 32;      // edge_dim
constexpr int HD  = 512;     // mlp hidden
constexpr int GG  = 64;      // graphs
constexpr float NEG  = 0.2f;
constexpr float EPSC = 1e-5f;

#define NEG_INF (__int_as_float(0xff800000u))

// ---------------- device scratch (no allocs allowed) ----------------
__device__ float g_xl  [NN * DD];
__device__ float g_xr  [NN * DD];
__device__ float g_xres[NN * DD];
__device__ float g_xtmp[NN * DD];
__device__ float g_x2  [NN * DD];
__device__ float g_xcur[NN * DD];
__device__ float g_h   [(size_t)NN * HD];
__device__ float g_alpha[(size_t)NE * NH];       // CSR-ordered: [pos][head]

__device__ int g_deg   [NN];
__device__ int g_rowptr[NN + 1];
__device__ int g_wp    [NN];
__device__ int g_pos   [NE];   // edge id -> CSR position
__device__ int g_src   [NE];   // CSR position -> src node
__device__ int g_gcnt  [GG];

__device__ float g_bnstat[2 * HD];
__device__ float g_bns[HD];
__device__ float g_bnt[HD];
__device__ float g_gstat[2 * GG];
__device__ float g_gmean[GG];
__device__ float g_ginv [GG];

// ---------------- setup kernels ----------------
__global__ void zero_init_kernel() {
    int i = blockIdx.x * blockDim.x + threadIdx.x;
    if (i < NN) g_deg[i] = 0;
    if (i < GG) g_gcnt[i] = 0;
}

__global__ void hist_kernel(const int* __restrict__ ei, const int* __restrict__ nb) {
    int i = blockIdx.x * blockDim.x + threadIdx.x;
    if (i < NE) atomicAdd(&g_deg[ei[NE + i]], 1);   // dst
    if (i < NN) atomicAdd(&g_gcnt[nb[i]], 1);
}

__global__ void scan_kernel() {
    __shared__ int part[1024];
    constexpr int CHUNK = (NN + 1023) / 1024;  // 49
    int t = threadIdx.x;
    int base = t * CHUNK;
    int s = 0;
    for (int i = 0; i < CHUNK; i++) {
        int idx = base + i;
        if (idx < NN) s += g_deg[idx];
    }
    part[t] = s;
    __syncthreads();
    for (int off = 1; off < 1024; off <<= 1) {
        int v = (t >= off) ? part[t - off] : 0;
        __syncthreads();
        part[t] += v;
        __syncthreads();
    }
    int run = (t == 0) ? 0 : part[t - 1];
    for (int i = 0; i < CHUNK; i++) {
        int idx = base + i;
        if (idx < NN) {
            g_rowptr[idx] = run;
            g_wp[idx] = run;
            run += g_deg[idx];
        }
    }
    if (t == 1023) g_rowptr[NN] = part[1023];
}

__global__ void scatter_kernel(const int* __restrict__ ei) {
    int e = blockIdx.x * blockDim.x + threadIdx.x;
    if (e >= NE) return;
    int s = ei[e];
    int d = ei[NE + e];
    int p = atomicAdd(&g_wp[d], 1);
    g_pos[e] = p;
    g_src[p] = s;
}

__global__ void zero_stats_kernel() {
    int i = blockIdx.x * blockDim.x + threadIdx.x;
    if (i < 2 * HD) g_bnstat[i] = 0.f;
    if (i < 2 * GG) g_gstat[i] = 0.f;
}

// ---------------- split-TF32 helpers (3-term compensated product) ----------------
__device__ __forceinline__ uint32_t to_tf32(float f) {
    uint32_t r;
    asm("cvt.rna.tf32.f32 %0, %1;" : "=r"(r) : "f"(f));
    return r;
}

__device__ __forceinline__ void split_tf32(float f, uint32_t& hi, uint32_t& lo) {
    hi = to_tf32(f);
    lo = to_tf32(f - __uint_as_float(hi));
}

__device__ __forceinline__ void mma_tf32(float c[4], const uint32_t a[4],
                                         uint32_t b0, uint32_t b1) {
    asm volatile(
        "mma.sync.aligned.m16n8k8.row.col.f32.tf32.tf32.f32 "
        "{%0,%1,%2,%3},{%4,%5,%6,%7},{%8,%9},{%0,%1,%2,%3};"
        : "+f"(c[0]), "+f"(c[1]), "+f"(c[2]), "+f"(c[3])
        : "r"(a[0]), "r"(a[1]), "r"(a[2]), "r"(a[3]), "r"(b0), "r"(b1));
}

// Shared GEMM core pieces: BM=128, BN=64, BK=16, 256 thr = 8 warps (4x2),
// warp tile 32x32 via m16n8k8, hi/lo operand split.
constexpr int BM = 128, BN = 64, BK = 16, PAD = 20;

struct GemmSmem {
    uint32_t Ahi[BM][PAD];
    uint32_t Alo[BM][PAD];
    uint32_t Whi[BN][PAD];
    uint32_t Wlo[BN][PAD];
};

// stage one k-tile of A (with optional BN+ReLU transform) and W into smem
__device__ __forceinline__ void stage_tile(GemmSmem& sm, const float* A,
                                           const float* W, const float* tS,
                                           const float* tT, int N, int K, int M,
                                           int rowBase, int colBase, int k0, int tid) {
    int arow = tid >> 1;
    int akq  = (tid & 1) * 8;
    {
        int grow = rowBase + arow;
        float v[8] = {0.f, 0.f, 0.f, 0.f, 0.f, 0.f, 0.f, 0.f};
        if (grow < N) {
            const float* ap = &A[(size_t)grow * K + k0 + akq];
            float4 v0 = *(const float4*)ap;
            float4 v1 = *(const float4*)(ap + 4);
            v[0] = v0.x; v[1] = v0.y; v[2] = v0.z; v[3] = v0.w;
            v[4] = v1.x; v[5] = v1.y; v[6] = v1.z; v[7] = v1.w;
            if (tS) {
                int gk = k0 + akq;
#pragma unroll
                for (int i = 0; i < 8; i++)
                    v[i] = fmaxf(fmaf(v[i], tS[gk + i], tT[gk + i]), 0.f);
            }
        }
#pragma unroll
        for (int i = 0; i < 8; i++) {
            uint32_t hi, lo;
            split_tf32(v[i], hi, lo);
            sm.Ahi[arow][akq + i] = hi;
            sm.Alo[arow][akq + i] = lo;
        }
    }
    {
        int bk = tid >> 4;
        int bn = (tid & 15) * 4;
        float4 wv = *(const float4*)&W[(size_t)(k0 + bk) * M + colBase + bn];
        float wa[4] = {wv.x, wv.y, wv.z, wv.w};
#pragma unroll
        for (int j = 0; j < 4; j++) {
            uint32_t hi, lo;
            split_tf32(wa[j], hi, lo);
            sm.Whi[bn + j][bk] = hi;
            sm.Wlo[bn + j][bk] = lo;
        }
    }
}

// mainloop body for one staged k-tile
__device__ __forceinline__ void mma_tile(GemmSmem& sm, float acc[2][4][4],
                                         int wr, int wc, int lq, int lr) {
#pragma unroll
    for (int ks = 0; ks < 2; ks++) {
        int kb = ks * 8;
        uint32_t ah[2][4], al[2][4];
#pragma unroll
        for (int mt = 0; mt < 2; mt++) {
            int r0 = wr * 32 + mt * 16 + lq;
            ah[mt][0] = sm.Ahi[r0][kb + lr];
            ah[mt][1] = sm.Ahi[r0 + 8][kb + lr];
            ah[mt][2] = sm.Ahi[r0][kb + 4 + lr];
            ah[mt][3] = sm.Ahi[r0 + 8][kb + 4 + lr];
            al[mt][0] = sm.Alo[r0][kb + lr];
            al[mt][1] = sm.Alo[r0 + 8][kb + lr];
            al[mt][2] = sm.Alo[r0][kb + 4 + lr];
            al[mt][3] = sm.Alo[r0 + 8][kb + 4 + lr];
        }
        uint32_t bh[4][2], bl[4][2];
#pragma unroll
        for (int nt = 0; nt < 4; nt++) {
            int n0 = wc * 32 + nt * 8 + lq;
            bh[nt][0] = sm.Whi[n0][kb + lr];
            bh[nt][1] = sm.Whi[n0][kb + 4 + lr];
            bl[nt][0] = sm.Wlo[n0][kb + lr];
            bl[nt][1] = sm.Wlo[n0][kb + 4 + lr];
        }
#pragma unroll
        for (int mt = 0; mt < 2; mt++)
#pragma unroll
            for (int nt = 0; nt < 4; nt++) {
                mma_tf32(acc[mt][nt], ah[mt], bh[nt][0], bh[nt][1]);
                mma_tf32(acc[mt][nt], ah[mt], bl[nt][0], bl[nt][1]);
                mma_tf32(acc[mt][nt], al[mt], bh[nt][0], bh[nt][1]);
            }
    }
}

__device__ __forceinline__ void gemm_epilogue(float acc[2][4][4], const float* bias,
                                              const float* add, float* C, int N, int M,
                                              int rowBase, int colBase,
                                              int wr, int wc, int lq, int lr) {
#pragma unroll
    for (int mt = 0; mt < 2; mt++) {
#pragma unroll
        for (int nt = 0; nt < 4; nt++) {
            int c = colBase + wc * 32 + nt * 8 + 2 * lr;
            float2 bv = make_float2(0.f, 0.f);
            if (bias) bv = *(const float2*)&bias[c];
            int r0 = rowBase + wr * 32 + mt * 16 + lq;
            int r1 = r0 + 8;
            if (r0 < N) {
                float2 o = make_float2(acc[mt][nt][0] + bv.x, acc[mt][nt][1] + bv.y);
                if (add) {
                    float2 av = *(const float2*)&add[(size_t)r0 * M + c];
                    o.x += av.x; o.y += av.y;
                }
                *(float2*)&C[(size_t)r0 * M + c] = o;
            }
            if (r1 < N) {
                float2 o = make_float2(acc[mt][nt][2] + bv.x, acc[mt][nt][3] + bv.y);
                if (add) {
                    float2 av = *(const float2*)&add[(size_t)r1 * M + c];
                    o.x += av.x; o.y += av.y;
                }
                *(float2*)&C[(size_t)r1 * M + c] = o;
            }
        }
    }
}

// generic GEMM (used for W1, W2 with transform/add)
__global__ __launch_bounds__(256)
void gemm_kernel(const float* __restrict__ A, const float* __restrict__ W,
                 const float* __restrict__ bias, const float* __restrict__ add,
                 const float* __restrict__ tS, const float* __restrict__ tT,
                 float* __restrict__ C, int N, int K, int M) {
    __shared__ GemmSmem sm;
    int tid  = threadIdx.x;
    int lane = tid & 31;
    int w    = tid >> 5;
    int wr = w >> 1, wc = w & 1, lq = lane >> 2, lr = lane & 3;
    int rowBase = blockIdx.x * BM;
    int colBase = blockIdx.y * BN;

    float acc[2][4][4];
#pragma unroll
    for (int mt = 0; mt < 2; mt++)
#pragma unroll
        for (int nt = 0; nt < 4; nt++)
#pragma unroll
            for (int i = 0; i < 4; i++) acc[mt][nt][i] = 0.f;

    for (int k0 = 0; k0 < K; k0 += BK) {
        stage_tile(sm, A, W, tS, tT, N, K, M, rowBase, colBase, k0, tid);
        __syncthreads();
        mma_tile(sm, acc, wr, wc, lq, lr);
        __syncthreads();
    }
    gemm_epilogue(acc, bias, add, C, N, M, rowBase, colBase, wr, wc, lq, lr);
}

// triple GEMM: shares A, computes xl/xr/xres in one launch. K=M=128 fixed.
// grid.y in 0..5: sel = y>>1 picks (W,bias,C); colBase = (y&1)*64.
__global__ __launch_bounds__(256)
void gemm3_kernel(const float* __restrict__ A,
                  const float* __restrict__ W0, const float* __restrict__ W1,
                  const float* __restrict__ W2,
                  const float* __restrict__ b0, const float* __restrict__ b1,
                  const float* __restrict__ b2,
                  float* __restrict__ C0, float* __restrict__ C1,
                  float* __restrict__ C2) {
    __shared__ GemmSmem sm;
    int tid  = threadIdx.x;
    int lane = tid & 31;
    int w    = tid >> 5;
    int wr = w >> 1, wc = w & 1, lq = lane >> 2, lr = lane & 3;
    int rowBase = blockIdx.x * BM;
    int sel     = blockIdx.y >> 1;
    int colBase = (blockIdx.y & 1) * BN;
    const float* W    = (sel == 0) ? W0 : (sel == 1) ? W1 : W2;
    const float* bias = (sel == 0) ? b0 : (sel == 1) ? b1 : b2;
    float* C          = (sel == 0) ? C0 : (sel == 1) ? C1 : C2;

    float acc[2][4][4];
#pragma unroll
    for (int mt = 0; mt < 2; mt++)
#pragma unroll
        for (int nt = 0; nt < 4; nt++)
#pragma unroll
            for (int i = 0; i < 4; i++) acc[mt][nt][i] = 0.f;

    for (int k0 = 0; k0 < DD; k0 += BK) {
        stage_tile(sm, A, W, nullptr, nullptr, NN, DD, DD, rowBase, colBase, k0, tid);
        __syncthreads();
        mma_tile(sm, acc, wr, wc, lq, lr);
        __syncthreads();
    }
    gemm_epilogue(acc, bias, nullptr, C, NN, DD, rowBase, colBase, wr, wc, lq, lr);
}

// ---------------- fused edge kernel: e-projection GEMM + leaky + att dot ----------------
__device__ __forceinline__ float lky(float v) { return v > 0.f ? v : NEG * v; }

__global__ __launch_bounds__(256)
void edge_fused_kernel(const int* __restrict__ ei, const float* __restrict__ ea,
                       const float* __restrict__ We, const float* __restrict__ att) {
    constexpr int TE = 128;
    constexpr int EW = 16;
    __shared__ float ea_s[TE * EDD];
    __shared__ float We_s[EDD * DD];
    __shared__ float att_s[DD];

    int tid  = threadIdx.x;
    int lane = tid & 31;
    int w    = tid >> 5;
    int e0   = blockIdx.x * TE;

    {
        const float4* We4 = (const float4*)We;
        float4* Ws4 = (float4*)We_s;
#pragma unroll
        for (int i = 0; i < 4; i++) Ws4[tid + 256 * i] = We4[tid + 256 * i];
        const float4* ea4 = (const float4*)(ea + (size_t)e0 * EDD);
        float4* es4 = (float4*)ea_s;
#pragma unroll
        for (int i = 0; i < 4; i++) es4[tid + 256 * i] = ea4[tid + 256 * i];
        if (tid < DD) att_s[tid] = att[tid];
    }
    __syncthreads();

    float acc[EW][4];
#pragma unroll
    for (int i = 0; i < EW; i++)
#pragma unroll
        for (int j = 0; j < 4; j++) acc[i][j] = 0.f;

#pragma unroll
    for (int k = 0; k < EDD; k++) {
        float4 wv = *(float4*)&We_s[k * DD + lane * 4];
#pragma unroll
        for (int i = 0; i < EW; i++) {
            float a = ea_s[(w * EW + i) * EDD + k];
            acc[i][0] = fmaf(a, wv.x, acc[i][0]);
            acc[i][1] = fmaf(a, wv.y, acc[i][1]);
            acc[i][2] = fmaf(a, wv.z, acc[i][2]);
            acc[i][3] = fmaf(a, wv.w, acc[i][3]);
        }
    }

    float4 attv = *(float4*)&att_s[lane * 4];

#pragma unroll 4
    for (int i = 0; i < EW; i++) {
        int e = e0 + w * EW + i;
        int s = ei[e];
        int d = ei[NE + e];
        float4 xlv = *(const float4*)&g_xl[(size_t)s * DD + lane * 4];
        float4 xrv = *(const float4*)&g_xr[(size_t)d * DD + lane * 4];
        float mx = lky(acc[i][0] + xlv.x + xrv.x);
        float my = lky(acc[i][1] + xlv.y + xrv.y);
        float mz = lky(acc[i][2] + xlv.z + xrv.z);
        float mw = lky(acc[i][3] + xlv.w + xrv.w);
        float p = mx * attv.x + my * attv.y + mz * attv.z + mw * attv.w;
        p += __shfl_xor_sync(0xffffffffu, p, 1);
        p += __shfl_xor_sync(0xffffffffu, p, 2);
        int pos = g_pos[e];
        if ((lane & 3) == 0) g_alpha[(size_t)pos * NH + (lane >> 2)] = p;
    }
}

// ---------------- node aggregation: online softmax, CSR-sequential streams ----------------
__global__ __launch_bounds__(256)
void node_agg_kernel() {
    int lane = threadIdx.x & 31;
    int n = blockIdx.x * 8 + (threadIdx.x >> 5);
    if (n >= NN) return;
    int h = lane >> 2;
    int beg = g_rowptr[n], end = g_rowptr[n + 1];
    float m = NEG_INF, den = 0.f;
    float4 acc = make_float4(0.f, 0.f, 0.f, 0.f);

    int j = beg;
    for (; j + 1 < end; j += 2) {
        float a0 = g_alpha[(size_t)j * NH + h];
        float a1 = g_alpha[(size_t)(j + 1) * NH + h];
        int   s0 = g_src[j];
        int   s1 = g_src[j + 1];
        float4 x0 = *(const float4*)&g_xl[(size_t)s0 * DD + lane * 4];
        float4 x1 = *(const float4*)&g_xl[(size_t)s1 * DD + lane * 4];

        float mn = fmaxf(m, a0);
        float corr = __expf(m - mn);
        float p = __expf(a0 - mn);
        den = den * corr + p;
        acc.x = acc.x * corr + p * x0.x;
        acc.y = acc.y * corr + p * x0.y;
        acc.z = acc.z * corr + p * x0.z;
        acc.w = acc.w * corr + p * x0.w;
        m = mn;

        mn = fmaxf(m, a1);
        corr = __expf(m - mn);
        p = __expf(a1 - mn);
        den = den * corr + p;
        acc.x = acc.x * corr + p * x1.x;
        acc.y = acc.y * corr + p * x1.y;
        acc.z = acc.z * corr + p * x1.z;
        acc.w = acc.w * corr + p * x1.w;
        m = mn;
    }
    for (; j < end; j++) {
        float a = g_alpha[(size_t)j * NH + h];
        int s = g_src[j];
        float4 xlv = *(const float4*)&g_xl[(size_t)s * DD + lane * 4];
        float mn = fmaxf(m, a);
        float corr = __expf(m - mn);
        float p = __expf(a - mn);
        den = den * corr + p;
        acc.x = acc.x * corr + p * xlv.x;
        acc.y = acc.y * corr + p * xlv.y;
        acc.z = acc.z * corr + p * xlv.z;
        acc.w = acc.w * corr + p * xlv.w;
        m = mn;
    }

    float inv = 1.f / (den + 1e-16f);
    float4 rv = *(const float4*)&g_xres[(size_t)n * DD + lane * 4];
    float4 o = make_float4(acc.x * inv + rv.x, acc.y * inv + rv.y,
                           acc.z * inv + rv.z, acc.w * inv + rv.w);
    *(float4*)&g_xtmp[(size_t)n * DD + lane * 4] = o;
}

// ---------------- BN column stats over g_h [NN, HD] ----------------
__global__ void colstats_kernel() {
    int col = blockIdx.x * 128 + threadIdx.x;
    constexpr int CHUNK = (NN + 63) / 64;  // 782
    int r0 = blockIdx.y * CHUNK;
    int r1 = min(r0 + CHUNK, NN);
    float s = 0.f, q = 0.f;
    for (int r = r0; r < r1; r++) {
        float v = g_h[(size_t)r * HD + col];
        s += v;
        q += v * v;
    }
    atomicAdd(&g_bnstat[col], s);
    atomicAdd(&g_bnstat[HD + col], q);
}

__global__ void bn_final_kernel(const float* __restrict__ gamma, const float* __restrict__ beta) {
    int c = threadIdx.x;
    if (c >= HD) return;
    float invn = 1.f / (float)NN;
    float mu  = g_bnstat[c] * invn;
    float var = g_bnstat[HD + c] * invn - mu * mu;
    float istd = rsqrtf(var + EPSC);
    float s = gamma[c] * istd;
    g_bns[c] = s;
    g_bnt[c] = beta[c] - mu * s;
}

// ---------------- graph LayerNorm stats over g_x2 ----------------
__global__ __launch_bounds__(256)
void ln_stats_kernel(const int* __restrict__ nb) {
    int lane = threadIdx.x & 31;
    int n = blockIdx.x * 8 + (threadIdx.x >> 5);
    if (n >= NN) return;
    float4 v = *(const float4*)&g_x2[(size_t)n * DD + lane * 4];
    float s = v.x + v.y + v.z + v.w;
    float q = v.x * v.x + v.y * v.y + v.z * v.z + v.w * v.w;
#pragma unroll
    for (int off = 16; off > 0; off >>= 1) {
        s += __shfl_xor_sync(0xffffffffu, s, off);
        q += __shfl_xor_sync(0xffffffffu, q, off);
    }
    if (lane == 0) {
        int g = nb[n];
        atomicAdd(&g_gstat[g], s);
        atomicAdd(&g_gstat[GG + g], q);
    }
}

__global__ void ln_final_kernel() {
    int g = threadIdx.x;
    if (g >= GG) return;
    float cnt = fmaxf((float)g_gcnt[g], 1.f);
    float denom = cnt * (float)DD;
    float mean = g_gstat[g] / denom;
    float var  = g_gstat[GG + g] / denom - mean * mean;
    g_gmean[g] = mean;
    g_ginv[g]  = rsqrtf(var + EPSC);
}

__global__ void ln_apply_kernel(const int* __restrict__ nb,
                                const float* __restrict__ gamma,
                                const float* __restrict__ beta,
                                float* __restrict__ dst) {
    int idx = blockIdx.x * blockDim.x + threadIdx.x;
    if (idx >= NN * (DD / 4)) return;
    int n  = idx >> 5;
    int c4 = (idx & 31) * 4;
    int g  = nb[n];
    float mean = g_gmean[g];
    float ginv = g_ginv[g];
    float4 v  = *(const float4*)&g_x2[(size_t)n * DD + c4];
    float4 ga = *(const float4*)&gamma[c4];
    float4 be = *(const float4*)&beta[c4];
    float4 o;
    o.x = (v.x - mean) * ginv * ga.x + be.x;
    o.y = (v.y - mean) * ginv * ga.y + be.y;
    o.z = (v.z - mean) * ginv * ga.z + be.z;
    o.w = (v.w - mean) * ginv * ga.w + be.w;
    *(float4*)&dst[(size_t)n * DD + c4] = o;
}

// ---------------- host launch ----------------
extern "C" void kernel_launch(void* const* d_in, const int* in_sizes, int n_in,
                              void* d_out, int out_size) {
    const float* x    = (const float*)d_in[0];
    const int*   nb   = (const int*)  d_in[1];
    const int*   ei   = (const int*)  d_in[2];
    const float* ea   = (const float*)d_in[3];
    const float* Wl   = (const float*)d_in[4];
    const float* bl   = (const float*)d_in[5];
    const float* Wr   = (const float*)d_in[6];
    const float* br   = (const float*)d_in[7];
    const float* We   = (const float*)d_in[8];
    const float* att  = (const float*)d_in[9];
    const float* bias = (const float*)d_in[10];
    const float* Wres = (const float*)d_in[11];
    const float* W1   = (const float*)d_in[12];
    const float* b1   = (const float*)d_in[13];
    const float* bng  = (const float*)d_in[14];
    const float* bnb  = (const float*)d_in[15];
    const float* W2   = (const float*)d_in[16];
    const float* b2   = (const float*)d_in[17];
    const float* lng  = (const float*)d_in[18];
    const float* lnb  = (const float*)d_in[19];
    float* out = (float*)d_out;

    void* p;
    cudaGetSymbolAddress(&p, g_xl);   float* pxl   = (float*)p;
    cudaGetSymbolAddress(&p, g_xr);   float* pxr   = (float*)p;
    cudaGetSymbolAddress(&p, g_xres); float* pxres = (float*)p;
    cudaGetSymbolAddress(&p, g_xtmp); float* pxtmp = (float*)p;
    cudaGetSymbolAddress(&p, g_x2);   float* px2   = (float*)p;
    cudaGetSymbolAddress(&p, g_xcur); float* pxcur = (float*)p;
    cudaGetSymbolAddress(&p, g_h);    float* ph    = (float*)p;
    cudaGetSymbolAddress(&p, g_bns);  float* pbns  = (float*)p;
    cudaGetSymbolAddress(&p, g_bnt);  float* pbnt  = (float*)p;

    const int GR = (NN + 127) / 128;   // 391

    // CSR prologue (launches 1-3); the layer-0 triple GEMM is launch #4 so the
    // ncu capture window (harness offset + -s 5) lands on it.
    zero_init_kernel<<<(NN + 255) / 256, 256>>>();
    hist_kernel<<<(NE + 255) / 256, 256>>>(ei, nb);
    scan_kernel<<<1, 1024>>>();

    const float* xin = x;
    for (int l = 0; l < 2; l++) {
        gemm3_kernel<<<dim3(GR, 6), 256>>>(xin,
            Wl + (size_t)l * DD * DD, Wr + (size_t)l * DD * DD, Wres + (size_t)l * DD * DD,
            bl + l * DD, br + l * DD, bias + l * DD,
            pxl, pxr, pxres);
        if (l == 0) scatter_kernel<<<(NE + 255) / 256, 256>>>(ei);
        zero_stats_kernel<<<2, 1024>>>();

        edge_fused_kernel<<<NE / 128, 256>>>(ei, ea, We + (size_t)l * EDD * DD, att + l * DD);
        node_agg_kernel<<<(NN + 7) / 8, 256>>>();

        gemm_kernel<<<dim3(GR, 8), 256>>>(pxtmp, W1 + (size_t)l * DD * HD, b1 + l * HD,
                                          nullptr, nullptr, nullptr, ph, NN, DD, HD);
        colstats_kernel<<<dim3(4, 64), 128>>>();
        bn_final_kernel<<<1, 512>>>(bng + l * HD, bnb + l * HD);
        gemm_kernel<<<dim3(GR, 2), 256>>>(ph, W2 + (size_t)l * HD * DD, b2 + l * DD,
                                          pxtmp, pbns, pbnt, px2, NN, HD, DD);

        ln_stats_kernel<<<(NN + 7) / 8, 256>>>(nb);
        ln_final_kernel<<<1, 64>>>();
        float* dst = (l == 1) ? out : pxcur;
        ln_apply_kernel<<<(NN * (DD / 4) + 255) / 256, 256>>>(nb, lng + l * DD, lnb + l * DD, dst);

        xin = pxcur;
    }
}

// round 9
// speedup vs baseline: 1.0857x; 1.0857x over previous
#include <cuda_runtime.h>
#include <cstdint>
#include <cstdio>

// ---------------- problem constants ----------------
constexpr int NN  = 50000;   // nodes
constexpr int NE  = 800000;  // edges
constexpr int DD  = 128;     // channels
constexpr int NH  = 8;       // heads
constexpr int EDD = 32;      // edge_dim
constexpr int HD  = 512;     // mlp hidden
constexpr int GG  = 64;      // graphs
constexpr float NEG  = 0.2f;
constexpr float EPSC = 1e-5f;

#define NEG_INF (__int_as_float(0xff800000u))

// ---------------- device scratch (no allocs allowed) ----------------
__device__ float g_xl  [NN * DD];
__device__ float g_xr  [NN * DD];
__device__ float g_xres[NN * DD];
__device__ float g_xtmp[NN * DD];
__device__ float g_x2  [NN * DD];
__device__ float g_xcur[NN * DD];
__device__ float g_h   [(size_t)NN * HD];
__device__ float g_alpha[(size_t)NE * NH];       // CSR-ordered: [pos][head]

__device__ int g_deg   [NN];
__device__ int g_rowptr[NN + 1];
__device__ int g_wp    [NN];
__device__ int g_pos   [NE];
__device__ int g_src   [NE];
__device__ int g_gcnt  [GG];

__device__ float g_bnstat[2 * HD];
__device__ float g_bns[HD];
__device__ float g_bnt[HD];
__device__ float g_gstat[2 * GG];
__device__ float g_gmean[GG];
__device__ float g_ginv [GG];

// ---------------- setup kernels ----------------
__global__ void zero_init_kernel() {
    int i = blockIdx.x * blockDim.x + threadIdx.x;
    if (i < NN) g_deg[i] = 0;
    if (i < GG) g_gcnt[i] = 0;
}

__global__ void hist_kernel(const int* __restrict__ ei, const int* __restrict__ nb) {
    int i = blockIdx.x * blockDim.x + threadIdx.x;
    if (i < NE) atomicAdd(&g_deg[ei[NE + i]], 1);
    if (i < NN) atomicAdd(&g_gcnt[nb[i]], 1);
}

__global__ void scan_kernel() {
    __shared__ int part[1024];
    constexpr int CHUNK = (NN + 1023) / 1024;
    int t = threadIdx.x;
    int base = t * CHUNK;
    int s = 0;
    for (int i = 0; i < CHUNK; i++) {
        int idx = base + i;
        if (idx < NN) s += g_deg[idx];
    }
    part[t] = s;
    __syncthreads();
    for (int off = 1; off < 1024; off <<= 1) {
        int v = (t >= off) ? part[t - off] : 0;
        __syncthreads();
        part[t] += v;
        __syncthreads();
    }
    int run = (t == 0) ? 0 : part[t - 1];
    for (int i = 0; i < CHUNK; i++) {
        int idx = base + i;
        if (idx < NN) {
            g_rowptr[idx] = run;
            g_wp[idx] = run;
            run += g_deg[idx];
        }
    }
    if (t == 1023) g_rowptr[NN] = part[1023];
}

__global__ void scatter_kernel(const int* __restrict__ ei) {
    int e = blockIdx.x * blockDim.x + threadIdx.x;
    if (e >= NE) return;
    int s = ei[e];
    int d = ei[NE + e];
    int p = atomicAdd(&g_wp[d], 1);
    g_pos[e] = p;
    g_src[p] = s;
}

__global__ void zero_stats_kernel() {
    int i = blockIdx.x * blockDim.x + threadIdx.x;
    if (i < 2 * HD) g_bnstat[i] = 0.f;
    if (i < 2 * GG) g_gstat[i] = 0.f;
}

// ---------------- split-TF32 helpers ----------------
__device__ __forceinline__ uint32_t to_tf32(float f) {
    uint32_t r;
    asm("cvt.rna.tf32.f32 %0, %1;" : "=r"(r) : "f"(f));
    return r;
}

__device__ __forceinline__ void split_tf32(float f, uint32_t& hi, uint32_t& lo) {
    hi = to_tf32(f);
    lo = to_tf32(f - __uint_as_float(hi));
}

__device__ __forceinline__ void mma_tf32(float c[4], const uint32_t a[4],
                                         uint32_t b0, uint32_t b1) {
    asm volatile(
        "mma.sync.aligned.m16n8k8.row.col.f32.tf32.tf32.f32 "
        "{%0,%1,%2,%3},{%4,%5,%6,%7},{%8,%9},{%0,%1,%2,%3};"
        : "+f"(c[0]), "+f"(c[1]), "+f"(c[2]), "+f"(c[3])
        : "r"(a[0]), "r"(a[1]), "r"(a[2]), "r"(a[3]), "r"(b0), "r"(b1));
}

// ---------------- TF32 split GEMM, fp32-in-smem, double-buffered ----------------
// BM=128, BN=128, BK=16. 256 threads = 8 warps; warp tile 64(M) x 32(N).
// wr = w>>2 (0..1), wc = w&3 (0..3).
// A smem: As[st][row][20] fp32, plain layout (PAD=20: frag loads conflict-free).
// B smem: Bs[st][n][20] fp32, element (n,k) at k ^ ((n>>3)&7) (load conflict-free).
constexpr int GBM = 128, GBN = 128, GBK = 16, GPAD = 20;

struct GemmPrefetch {
    float4 a0, a1, b0, b1;
};

__device__ __forceinline__ void gemm_ldg(GemmPrefetch& pf, const float* A,
                                         const float* W, const float* tS,
                                         const float* tT, int N, int K, int M,
                                         int rowBase, int colBase, int k0, int tid) {
    int arow = tid >> 1;
    int akq  = (tid & 1) * 8;
    int grow = rowBase + arow;
    pf.a0 = make_float4(0.f, 0.f, 0.f, 0.f);
    pf.a1 = pf.a0;
    if (grow < N) {
        const float* ap = &A[(size_t)grow * K + k0 + akq];
        pf.a0 = *(const float4*)ap;
        pf.a1 = *(const float4*)(ap + 4);
        if (tS) {
            int gk = k0 + akq;
            float4 s0 = *(const float4*)&tS[gk];
            float4 s1 = *(const float4*)&tS[gk + 4];
            float4 t0 = *(const float4*)&tT[gk];
            float4 t1 = *(const float4*)&tT[gk + 4];
            pf.a0.x = fmaxf(fmaf(pf.a0.x, s0.x, t0.x), 0.f);
            pf.a0.y = fmaxf(fmaf(pf.a0.y, s0.y, t0.y), 0.f);
            pf.a0.z = fmaxf(fmaf(pf.a0.z, s0.z, t0.z), 0.f);
            pf.a0.w = fmaxf(fmaf(pf.a0.w, s0.w, t0.w), 0.f);
            pf.a1.x = fmaxf(fmaf(pf.a1.x, s1.x, t1.x), 0.f);
            pf.a1.y = fmaxf(fmaf(pf.a1.y, s1.y, t1.y), 0.f);
            pf.a1.z = fmaxf(fmaf(pf.a1.z, s1.z, t1.z), 0.f);
            pf.a1.w = fmaxf(fmaf(pf.a1.w, s1.w, t1.w), 0.f);
        }
    }
    int kp = tid >> 5;          // 0..7
    int nq = tid & 31;          // n = 4*nq .. +3
    const float* wp0 = &W[(size_t)(k0 + kp) * M + colBase + nq * 4];
    const float* wp1 = &W[(size_t)(k0 + kp + 8) * M + colBase + nq * 4];
    pf.b0 = *(const float4*)wp0;
    pf.b1 = *(const float4*)wp1;
}

__device__ __forceinline__ void gemm_sts(const GemmPrefetch& pf,
                                         float (*As)[GPAD], float (*Bs)[GPAD],
                                         int tid) {
    int arow = tid >> 1;
    int akq  = (tid & 1) * 8;
    *(float4*)&As[arow][akq]     = pf.a0;
    *(float4*)&As[arow][akq + 4] = pf.a1;

    int kp = tid >> 5;
    int nq = tid & 31;
    float b0[4] = {pf.b0.x, pf.b0.y, pf.b0.z, pf.b0.w};
    float b1[4] = {pf.b1.x, pf.b1.y, pf.b1.z, pf.b1.w};
#pragma unroll
    for (int jj = 0; jj < 4; jj++) {
        int n = nq * 4 + jj;
        int swz = (n >> 3) & 7;
        Bs[n][kp ^ swz]       = b0[jj];
        Bs[n][(kp + 8) ^ swz] = b1[jj];
    }
}

__device__ __forceinline__ void gemm_mma(const float (*As)[GPAD],
                                         const float (*Bs)[GPAD],
                                         float acc[4][4][4],
                                         int wr, int wc, int lq, int lr) {
#pragma unroll
    for (int ks = 0; ks < 2; ks++) {
        int kb = ks * 8;
        uint32_t ah[4][4], al[4][4];
#pragma unroll
        for (int mt = 0; mt < 4; mt++) {
            int r0 = wr * 64 + mt * 16 + lq;
            float f0 = As[r0][kb + lr];
            float f1 = As[r0 + 8][kb + lr];
            float f2 = As[r0][kb + 4 + lr];
            float f3 = As[r0 + 8][kb + 4 + lr];
            split_tf32(f0, ah[mt][0], al[mt][0]);
            split_tf32(f1, ah[mt][1], al[mt][1]);
            split_tf32(f2, ah[mt][2], al[mt][2]);
            split_tf32(f3, ah[mt][3], al[mt][3]);
        }
        uint32_t bh[4][2], bl[4][2];
#pragma unroll
        for (int nt = 0; nt < 4; nt++) {
            int n0 = wc * 32 + nt * 8 + lq;
            int swz = (wc * 4 + nt) & 7;
            float f0 = Bs[n0][(kb + lr) ^ swz];
            float f1 = Bs[n0][(kb + 4 + lr) ^ swz];
            split_tf32(f0, bh[nt][0], bl[nt][0]);
            split_tf32(f1, bh[nt][1], bl[nt][1]);
        }
#pragma unroll
        for (int mt = 0; mt < 4; mt++)
#pragma unroll
            for (int nt = 0; nt < 4; nt++) {
                mma_tf32(acc[mt][nt], ah[mt], bh[nt][0], bh[nt][1]);
                mma_tf32(acc[mt][nt], ah[mt], bl[nt][0], bl[nt][1]);
                mma_tf32(acc[mt][nt], al[mt], bh[nt][0], bh[nt][1]);
            }
    }
}

__device__ __forceinline__ void gemm_epilogue(float acc[4][4][4], const float* bias,
                                              const float* add, float* C, int N, int M,
                                              int rowBase, int colBase,
                                              int wr, int wc, int lq, int lr) {
#pragma unroll
    for (int mt = 0; mt < 4; mt++) {
#pragma unroll
        for (int nt = 0; nt < 4; nt++) {
            int c = colBase + wc * 32 + nt * 8 + 2 * lr;
            float2 bv = make_float2(0.f, 0.f);
            if (bias) bv = *(const float2*)&bias[c];
            int r0 = rowBase + wr * 64 + mt * 16 + lq;
            int r1 = r0 + 8;
            if (r0 < N) {
                float2 o = make_float2(acc[mt][nt][0] + bv.x, acc[mt][nt][1] + bv.y);
                if (add) {
                    float2 av = *(const float2*)&add[(size_t)r0 * M + c];
                    o.x += av.x; o.y += av.y;
                }
                *(float2*)&C[(size_t)r0 * M + c] = o;
            }
            if (r1 < N) {
                float2 o = make_float2(acc[mt][nt][2] + bv.x, acc[mt][nt][3] + bv.y);
                if (add) {
                    float2 av = *(const float2*)&add[(size_t)r1 * M + c];
                    o.x += av.x; o.y += av.y;
                }
                *(float2*)&C[(size_t)r1 * M + c] = o;
            }
        }
    }
}

__device__ __forceinline__ void gemm_core(const float* A, const float* W,
                                          const float* bias, const float* add,
                                          const float* tS, const float* tT,
                                          float* C, int N, int K, int M,
                                          int rowBase, int colBase,
                                          float (*As)[GBM][GPAD], float (*Bs)[GBN][GPAD]) {
    int tid  = threadIdx.x;
    int lane = tid & 31;
    int w    = tid >> 5;
    int wr = w >> 2, wc = w & 3, lq = lane >> 2, lr = lane & 3;

    float acc[4][4][4];
#pragma unroll
    for (int mt = 0; mt < 4; mt++)
#pragma unroll
        for (int nt = 0; nt < 4; nt++)
#pragma unroll
            for (int i = 0; i < 4; i++) acc[mt][nt][i] = 0.f;

    GemmPrefetch pf;
    gemm_ldg(pf, A, W, tS, tT, N, K, M, rowBase, colBase, 0, tid);
    gemm_sts(pf, As[0], Bs[0], tid);
    __syncthreads();

    int nk = K / GBK;
    for (int t = 0; t < nk; t++) {
        if (t + 1 < nk)
            gemm_ldg(pf, A, W, tS, tT, N, K, M, rowBase, colBase, (t + 1) * GBK, tid);
        gemm_mma(As[t & 1], Bs[t & 1], acc, wr, wc, lq, lr);
        if (t + 1 < nk)
            gemm_sts(pf, As[(t + 1) & 1], Bs[(t + 1) & 1], tid);
        __syncthreads();
    }
    gemm_epilogue(acc, bias, add, C, N, M, rowBase, colBase, wr, wc, lq, lr);
}

// generic GEMM (W1, W2 with transform/add)
__global__ __launch_bounds__(256)
void gemm_kernel(const float* __restrict__ A, const float* __restrict__ W,
                 const float* __restrict__ bias, const float* __restrict__ add,
                 const float* __restrict__ tS, const float* __restrict__ tT,
                 float* __restrict__ C, int N, int K, int M) {
    __shared__ float As[2][GBM][GPAD];
    __shared__ float Bs[2][GBN][GPAD];
    gemm_core(A, W, bias, add, tS, tT, C, N, K, M,
              blockIdx.x * GBM, blockIdx.y * GBN, As, Bs);
}

// triple GEMM: shares A, computes xl/xr/xres. K=M=128. grid.y = 0..2 selects output.
__global__ __launch_bounds__(256)
void gemm3_kernel(const float* __restrict__ A,
                  const float* __restrict__ W0, const float* __restrict__ W1,
                  const float* __restrict__ W2,
                  const float* __restrict__ b0, const float* __restrict__ b1,
                  const float* __restrict__ b2,
                  float* __restrict__ C0, float* __restrict__ C1,
                  float* __restrict__ C2) {
    __shared__ float As[2][GBM][GPAD];
    __shared__ float Bs[2][GBN][GPAD];
    int sel = blockIdx.y;
    const float* W    = (sel == 0) ? W0 : (sel == 1) ? W1 : W2;
    const float* bias = (sel == 0) ? b0 : (sel == 1) ? b1 : b2;
    float* C          = (sel == 0) ? C0 : (sel == 1) ? C1 : C2;
    gemm_core(A, W, bias, nullptr, nullptr, nullptr, C, NN, DD, DD,
              blockIdx.x * GBM, 0, As, Bs);
}

// ---------------- fused edge kernel ----------------
__device__ __forceinline__ float lky(float v) { return v > 0.f ? v : NEG * v; }

__global__ __launch_bounds__(256)
void edge_fused_kernel(const int* __restrict__ ei, const float* __restrict__ ea,
                       const float* __restrict__ We, const float* __restrict__ att) {
    constexpr int TE = 128;
    constexpr int EW = 16;
    __shared__ float ea_s[TE * EDD];
    __shared__ float We_s[EDD * DD];
    __shared__ float att_s[DD];

    int tid  = threadIdx.x;
    int lane = tid & 31;
    int w    = tid >> 5;
    int e0   = blockIdx.x * TE;

    {
        const float4* We4 = (const float4*)We;
        float4* Ws4 = (float4*)We_s;
#pragma unroll
        for (int i = 0; i < 4; i++) Ws4[tid + 256 * i] = We4[tid + 256 * i];
        const float4* ea4 = (const float4*)(ea + (size_t)e0 * EDD);
        float4* es4 = (float4*)ea_s;
#pragma unroll
        for (int i = 0; i < 4; i++) es4[tid + 256 * i] = ea4[tid + 256 * i];
        if (tid < DD) att_s[tid] = att[tid];
    }
    __syncthreads();

    float acc[EW][4];
#pragma unroll
    for (int i = 0; i < EW; i++)
#pragma unroll
        for (int j = 0; j < 4; j++) acc[i][j] = 0.f;

#pragma unroll
    for (int k = 0; k < EDD; k++) {
        float4 wv = *(float4*)&We_s[k * DD + lane * 4];
#pragma unroll
        for (int i = 0; i < EW; i++) {
            float a = ea_s[(w * EW + i) * EDD + k];
            acc[i][0] = fmaf(a, wv.x, acc[i][0]);
            acc[i][1] = fmaf(a, wv.y, acc[i][1]);
            acc[i][2] = fmaf(a, wv.z, acc[i][2]);
            acc[i][3] = fmaf(a, wv.w, acc[i][3]);
        }
    }

    float4 attv = *(float4*)&att_s[lane * 4];

#pragma unroll 4
    for (int i = 0; i < EW; i++) {
        int e = e0 + w * EW + i;
        int s = ei[e];
        int d = ei[NE + e];
        float4 xlv = *(const float4*)&g_xl[(size_t)s * DD + lane * 4];
        float4 xrv = *(const float4*)&g_xr[(size_t)d * DD + lane * 4];
        float mx = lky(acc[i][0] + xlv.x + xrv.x);
        float my = lky(acc[i][1] + xlv.y + xrv.y);
        float mz = lky(acc[i][2] + xlv.z + xrv.z);
        float mw = lky(acc[i][3] + xlv.w + xrv.w);
        float p = mx * attv.x + my * attv.y + mz * attv.z + mw * attv.w;
        p += __shfl_xor_sync(0xffffffffu, p, 1);
        p += __shfl_xor_sync(0xffffffffu, p, 2);
        int pos = g_pos[e];
        if ((lane & 3) == 0) g_alpha[(size_t)pos * NH + (lane >> 2)] = p;
    }
}

// ---------------- node aggregation ----------------
__global__ __launch_bounds__(256)
void node_agg_kernel() {
    int lane = threadIdx.x & 31;
    int n = blockIdx.x * 8 + (threadIdx.x >> 5);
    if (n >= NN) return;
    int h = lane >> 2;
    int beg = g_rowptr[n], end = g_rowptr[n + 1];
    float m = NEG_INF, den = 0.f;
    float4 acc = make_float4(0.f, 0.f, 0.f, 0.f);

    int j = beg;
    for (; j + 1 < end; j += 2) {
        float a0 = g_alpha[(size_t)j * NH + h];
        float a1 = g_alpha[(size_t)(j + 1) * NH + h];
        int   s0 = g_src[j];
        int   s1 = g_src[j + 1];
        float4 x0 = *(const float4*)&g_xl[(size_t)s0 * DD + lane * 4];
        float4 x1 = *(const float4*)&g_xl[(size_t)s1 * DD + lane * 4];

        float mn = fmaxf(m, a0);
        float corr = __expf(m - mn);
        float p = __expf(a0 - mn);
        den = den * corr + p;
        acc.x = acc.x * corr + p * x0.x;
        acc.y = acc.y * corr + p * x0.y;
        acc.z = acc.z * corr + p * x0.z;
        acc.w = acc.w * corr + p * x0.w;
        m = mn;

        mn = fmaxf(m, a1);
        corr = __expf(m - mn);
        p = __expf(a1 - mn);
        den = den * corr + p;
        acc.x = acc.x * corr + p * x1.x;
        acc.y = acc.y * corr + p * x1.y;
        acc.z = acc.z * corr + p * x1.z;
        acc.w = acc.w * corr + p * x1.w;
        m = mn;
    }
    for (; j < end; j++) {
        float a = g_alpha[(size_t)j * NH + h];
        int s = g_src[j];
        float4 xlv = *(const float4*)&g_xl[(size_t)s * DD + lane * 4];
        float mn = fmaxf(m, a);
        float corr = __expf(m - mn);
        float p = __expf(a - mn);
        den = den * corr + p;
        acc.x = acc.x * corr + p * xlv.x;
        acc.y = acc.y * corr + p * xlv.y;
        acc.z = acc.z * corr + p * xlv.z;
        acc.w = acc.w * corr + p * xlv.w;
        m = mn;
    }

    float inv = 1.f / (den + 1e-16f);
    float4 rv = *(const float4*)&g_xres[(size_t)n * DD + lane * 4];
    float4 o = make_float4(acc.x * inv + rv.x, acc.y * inv + rv.y,
                           acc.z * inv + rv.z, acc.w * inv + rv.w);
    *(float4*)&g_xtmp[(size_t)n * DD + lane * 4] = o;
}

// ---------------- BN column stats ----------------
__global__ void colstats_kernel() {
    int col = blockIdx.x * 128 + threadIdx.x;
    constexpr int CHUNK = (NN + 63) / 64;
    int r0 = blockIdx.y * CHUNK;
    int r1 = min(r0 + CHUNK, NN);
    float s = 0.f, q = 0.f;
    for (int r = r0; r < r1; r++) {
        float v = g_h[(size_t)r * HD + col];
        s += v;
        q += v * v;
    }
    atomicAdd(&g_bnstat[col], s);
    atomicAdd(&g_bnstat[HD + col], q);
}

__global__ void bn_final_kernel(const float* __restrict__ gamma, const float* __restrict__ beta) {
    int c = threadIdx.x;
    if (c >= HD) return;
    float invn = 1.f / (float)NN;
    float mu  = g_bnstat[c] * invn;
    float var = g_bnstat[HD + c] * invn - mu * mu;
    float istd = rsqrtf(var + EPSC);
    float s = gamma[c] * istd;
    g_bns[c] = s;
    g_bnt[c] = beta[c] - mu * s;
}

// ---------------- graph LayerNorm ----------------
__global__ __launch_bounds__(256)
void ln_stats_kernel(const int* __restrict__ nb) {
    int lane = threadIdx.x & 31;
    int n = blockIdx.x * 8 + (threadIdx.x >> 5);
    if (n >= NN) return;
    float4 v = *(const float4*)&g_x2[(size_t)n * DD + lane * 4];
    float s = v.x + v.y + v.z + v.w;
    float q = v.x * v.x + v.y * v.y + v.z * v.z + v.w * v.w;
#pragma unroll
    for (int off = 16; off > 0; off >>= 1) {
        s += __shfl_xor_sync(0xffffffffu, s, off);
        q += __shfl_xor_sync(0xffffffffu, q, off);
    }
    if (lane == 0) {
        int g = nb[n];
        atomicAdd(&g_gstat[g], s);
        atomicAdd(&g_gstat[GG + g], q);
    }
}

__global__ void ln_final_kernel() {
    int g = threadIdx.x;
    if (g >= GG) return;
    float cnt = fmaxf((float)g_gcnt[g], 1.f);
    float denom = cnt * (float)DD;
    float mean = g_gstat[g] / denom;
    float var  = g_gstat[GG + g] / denom - mean * mean;
    g_gmean[g] = mean;
    g_ginv[g]  = rsqrtf(var + EPSC);
}

__global__ void ln_apply_kernel(const int* __restrict__ nb,
                                const float* __restrict__ gamma,
                                const float* __restrict__ beta,
                                float* __restrict__ dst) {
    int idx = blockIdx.x * blockDim.x + threadIdx.x;
    if (idx >= NN * (DD / 4)) return;
    int n  = idx >> 5;
    int c4 = (idx & 31) * 4;
    int g  = nb[n];
    float mean = g_gmean[g];
    float ginv = g_ginv[g];
    float4 v  = *(const float4*)&g_x2[(size_t)n * DD + c4];
    float4 ga = *(const float4*)&gamma[c4];
    float4 be = *(const float4*)&beta[c4];
    float4 o;
    o.x = (v.x - mean) * ginv * ga.x + be.x;
    o.y = (v.y - mean) * ginv * ga.y + be.y;
    o.z = (v.z - mean) * ginv * ga.z + be.z;
    o.w = (v.w - mean) * ginv * ga.w + be.w;
    *(float4*)&dst[(size_t)n * DD + c4] = o;
}

// ---------------- host launch ----------------
extern "C" void kernel_launch(void* const* d_in, const int* in_sizes, int n_in,
                              void* d_out, int out_size) {
    const float* x    = (const float*)d_in[0];
    const int*   nb   = (const int*)  d_in[1];
    const int*   ei   = (const int*)  d_in[2];
    const float* ea   = (const float*)d_in[3];
    const float* Wl   = (const float*)d_in[4];
    const float* bl   = (const float*)d_in[5];
    const float* Wr   = (const float*)d_in[6];
    const float* br   = (const float*)d_in[7];
    const float* We   = (const float*)d_in[8];
    const float* att  = (const float*)d_in[9];
    const float* bias = (const float*)d_in[10];
    const float* Wres = (const float*)d_in[11];
    const float* W1   = (const float*)d_in[12];
    const float* b1   = (const float*)d_in[13];
    const float* bng  = (const float*)d_in[14];
    const float* bnb  = (const float*)d_in[15];
    const float* W2   = (const float*)d_in[16];
    const float* b2   = (const float*)d_in[17];
    const float* lng  = (const float*)d_in[18];
    const float* lnb  = (const float*)d_in[19];
    float* out = (float*)d_out;

    void* p;
    cudaGetSymbolAddress(&p, g_xl);   float* pxl   = (float*)p;
    cudaGetSymbolAddress(&p, g_xr);   float* pxr   = (float*)p;
    cudaGetSymbolAddress(&p, g_xres); float* pxres = (float*)p;
    cudaGetSymbolAddress(&p, g_xtmp); float* pxtmp = (float*)p;
    cudaGetSymbolAddress(&p, g_x2);   float* px2   = (float*)p;
    cudaGetSymbolAddress(&p, g_xcur); float* pxcur = (float*)p;
    cudaGetSymbolAddress(&p, g_h);    float* ph    = (float*)p;
    cudaGetSymbolAddress(&p, g_bns);  float* pbns  = (float*)p;
    cudaGetSymbolAddress(&p, g_bnt);  float* pbnt  = (float*)p;

    const int GR = (NN + 127) / 128;   // 391

    // launches 1-3 (CSR prologue); layer-0 gemm3 is launch #4 for the ncu window
    zero_init_kernel<<<(NN + 255) / 256, 256>>>();
    hist_kernel<<<(NE + 255) / 256, 256>>>(ei, nb);
    scan_kernel<<<1, 1024>>>();

    const float* xin = x;
    for (int l = 0; l < 2; l++) {
        gemm3_kernel<<<dim3(GR, 3), 256>>>(xin,
            Wl + (size_t)l * DD * DD, Wr + (size_t)l * DD * DD, Wres + (size_t)l * DD * DD,
            bl + l * DD, br + l * DD, bias + l * DD,
            pxl, pxr, pxres);
        if (l == 0) scatter_kernel<<<(NE + 255) / 256, 256>>>(ei);
        zero_stats_kernel<<<2, 1024>>>();

        edge_fused_kernel<<<NE / 128, 256>>>(ei, ea, We + (size_t)l * EDD * DD, att + l * DD);
        node_agg_kernel<<<(NN + 7) / 8, 256>>>();

        gemm_kernel<<<dim3(GR, 4), 256>>>(pxtmp, W1 + (size_t)l * DD * HD, b1 + l * HD,
                                          nullptr, nullptr, nullptr, ph, NN, DD, HD);
        colstats_kernel<<<dim3(4, 64), 128>>>();
        bn_final_kernel<<<1, 512>>>(bng + l * HD, bnb + l * HD);
        gemm_kernel<<<dim3(GR, 1), 256>>>(ph, W2 + (size_t)l * HD * DD, b2 + l * DD,
                                          pxtmp, pbns, pbnt, px2, NN, HD, DD);

        ln_stats_kernel<<<(NN + 7) / 8, 256>>>(nb);
        ln_final_kernel<<<1, 64>>>();
        float* dst = (l == 1) ? out : pxcur;
        ln_apply_kernel<<<(NN * (DD / 4) + 255) / 256, 256>>>(nb, lng + l * DD, lnb + l * DD, dst);

        xin = pxcur;
    }
}

// round 10
// speedup vs baseline: 1.1960x; 1.1016x over previous
#include <cuda_runtime.h>
#include <cstdint>
#include <cstdio>

// ---------------- problem constants ----------------
constexpr int NN  = 50000;   // nodes
constexpr int NE  = 800000;  // edges
constexpr int DD  = 128;     // channels
constexpr int NH  = 8;       // heads
constexpr int EDD = 32;      // edge_dim
constexpr int HD  = 512;     // mlp hidden
constexpr int GG  = 64;      // graphs
constexpr float NEG  = 0.2f;
constexpr float EPSC = 1e-5f;

#define NEG_INF (__int_as_float(0xff800000u))

// ---------------- device scratch ----------------
__device__ float g_xl  [NN * DD];
__device__ float g_xr  [NN * DD];
__device__ float g_xres[NN * DD];
__device__ float g_xtmp[NN * DD];
__device__ float g_x2  [NN * DD];
__device__ float g_xcur[NN * DD];
__device__ float g_h   [(size_t)NN * HD];
__device__ float g_alpha[(size_t)NE * NH];       // CSR-ordered: [pos][head]

__device__ int g_deg   [NN];
__device__ int g_rowptr[NN + 1];
__device__ int g_wp    [NN];
__device__ int g_pos   [NE];
__device__ int g_src   [NE];
__device__ int g_gcnt  [GG];

__device__ float g_bnstat[2 * HD];
__device__ float g_bns[HD];
__device__ float g_bnt[HD];
__device__ float g_gstat[2 * GG];
__device__ float g_gmean[GG];
__device__ float g_ginv [GG];

// ---------------- setup kernels ----------------
__global__ void zero_init_kernel() {
    int i = blockIdx.x * blockDim.x + threadIdx.x;
    if (i < NN) g_deg[i] = 0;
    if (i < GG) g_gcnt[i] = 0;
}

__global__ void hist_kernel(const int* __restrict__ ei, const int* __restrict__ nb) {
    int i = blockIdx.x * blockDim.x + threadIdx.x;
    if (i < NE) atomicAdd(&g_deg[ei[NE + i]], 1);
    if (i < NN) atomicAdd(&g_gcnt[nb[i]], 1);
}

__global__ void scan_kernel() {
    __shared__ int part[1024];
    constexpr int CHUNK = (NN + 1023) / 1024;
    int t = threadIdx.x;
    int base = t * CHUNK;
    int s = 0;
    for (int i = 0; i < CHUNK; i++) {
        int idx = base + i;
        if (idx < NN) s += g_deg[idx];
    }
    part[t] = s;
    __syncthreads();
    for (int off = 1; off < 1024; off <<= 1) {
        int v = (t >= off) ? part[t - off] : 0;
        __syncthreads();
        part[t] += v;
        __syncthreads();
    }
    int run = (t == 0) ? 0 : part[t - 1];
    for (int i = 0; i < CHUNK; i++) {
        int idx = base + i;
        if (idx < NN) {
            g_rowptr[idx] = run;
            g_wp[idx] = run;
            run += g_deg[idx];
        }
    }
    if (t == 1023) g_rowptr[NN] = part[1023];
}

__global__ void scatter_kernel(const int* __restrict__ ei) {
    int e = blockIdx.x * blockDim.x + threadIdx.x;
    if (e >= NE) return;
    int s = ei[e];
    int d = ei[NE + e];
    int p = atomicAdd(&g_wp[d], 1);
    g_pos[e] = p;
    g_src[p] = s;
}

__global__ void zero_stats_kernel() {
    int i = blockIdx.x * blockDim.x + threadIdx.x;
    if (i < 2 * HD) g_bnstat[i] = 0.f;
    if (i < 2 * GG) g_gstat[i] = 0.f;
}

// ---------------- split-TF32 + cp.async helpers ----------------
__device__ __forceinline__ uint32_t to_tf32(float f) {
    uint32_t r;
    asm("cvt.rna.tf32.f32 %0, %1;" : "=r"(r) : "f"(f));
    return r;
}

__device__ __forceinline__ void split_tf32(float f, uint32_t& hi, uint32_t& lo) {
    hi = to_tf32(f);
    lo = to_tf32(f - __uint_as_float(hi));
}

__device__ __forceinline__ void mma_tf32(float c[4], const uint32_t a[4],
                                         uint32_t b0, uint32_t b1) {
    asm volatile(
        "mma.sync.aligned.m16n8k8.row.col.f32.tf32.tf32.f32 "
        "{%0,%1,%2,%3},{%4,%5,%6,%7},{%8,%9},{%0,%1,%2,%3};"
        : "+f"(c[0]), "+f"(c[1]), "+f"(c[2]), "+f"(c[3])
        : "r"(a[0]), "r"(a[1]), "r"(a[2]), "r"(a[3]), "r"(b0), "r"(b1));
}

__device__ __forceinline__ void cp16(uint32_t dst, const void* src, bool valid) {
    int sz = valid ? 16 : 0;
    asm volatile("cp.async.ca.shared.global [%0], [%1], 16, %2;"
                 :: "r"(dst), "l"(src), "r"(sz));
}
__device__ __forceinline__ void cp_commit() {
    asm volatile("cp.async.commit_group;");
}
template <int NW>
__device__ __forceinline__ void cp_wait() {
    asm volatile("cp.async.wait_group %0;" :: "n"(NW));
}

// ---------------- TF32 split GEMM, cp.async double-buffered ----------------
// BM=128, BN=128, BK=16. 256 threads = 8 warps; warp tile 64(M) x 32(N).
// A smem: As[row][20] fp32  (frag banks 20*lq+lr: conflict-free)
// B smem: Bs[k][136] fp32, k-major (frag banks 8*lr+lq: conflict-free)
constexpr int GBM = 128, GBN = 128, GBK = 16;
constexpr int APAD = 20;    // A row stride (words)
constexpr int BSTR = 136;   // B k-row stride (words)
constexpr int A_WORDS = GBM * APAD;   // 2560
constexpr int B_WORDS = GBK * BSTR;   // 2176

// issue cp.async for one k-tile into stage buffer
__device__ __forceinline__ void gemm_stage(float* As, float* Bs,
                                           const float* A, const float* W,
                                           int N, int K, int M,
                                           int rowBase, int colBase, int k0, int tid) {
    // A: 128 rows x 16 floats = 512 x 16B chunks; thread t does chunks 2t, 2t+1
    int c0   = tid * 2;
    int arow = c0 >> 2;
    int akq  = (c0 & 3) * 4;
    int grow = rowBase + arow;
    bool av  = grow < N;
    const float* asrc = &A[(size_t)grow * K + k0 + akq];
    uint32_t adst = (uint32_t)__cvta_generic_to_shared(&As[arow * APAD + akq]);
    cp16(adst, asrc, av);
    cp16(adst + 16, asrc + 4, av);
    // B: 16 k-rows x 128 floats = 512 x 16B chunks; thread t does k=t>>5 and k+8
    int bk = tid >> 5;
    int bn = (tid & 31) * 4;
    const float* bsrc0 = &W[(size_t)(k0 + bk) * M + colBase + bn];
    const float* bsrc1 = &W[(size_t)(k0 + bk + 8) * M + colBase + bn];
    cp16((uint32_t)__cvta_generic_to_shared(&Bs[bk * BSTR + bn]), bsrc0, true);
    cp16((uint32_t)__cvta_generic_to_shared(&Bs[(bk + 8) * BSTR + bn]), bsrc1, true);
}

__device__ __forceinline__ void gemm_mma(const float* As, const float* Bs,
                                         float acc[4][4][4],
                                         int wr, int wc, int lq, int lr,
                                         const float* tS, const float* tT, int k0) {
#pragma unroll
    for (int ks = 0; ks < 2; ks++) {
        int kb = ks * 8;
        uint32_t bh[4][2], bl[4][2];
#pragma unroll
        for (int nt = 0; nt < 4; nt++) {
            int n0 = wc * 32 + nt * 8 + lq;
            split_tf32(Bs[(kb + lr) * BSTR + n0], bh[nt][0], bl[nt][0]);
            split_tf32(Bs[(kb + 4 + lr) * BSTR + n0], bh[nt][1], bl[nt][1]);
        }
        float s0 = 0.f, t0 = 0.f, s1 = 0.f, t1 = 0.f;
        bool tf = (tS != nullptr);
        if (tf) {
            s0 = tS[k0 + kb + lr];     t0 = tT[k0 + kb + lr];
            s1 = tS[k0 + kb + 4 + lr]; t1 = tT[k0 + kb + 4 + lr];
        }
#pragma unroll
        for (int mt = 0; mt < 4; mt++) {
            int r0 = wr * 64 + mt * 16 + lq;
            float f0 = As[r0 * APAD + kb + lr];
            float f1 = As[(r0 + 8) * APAD + kb + lr];
            float f2 = As[r0 * APAD + kb + 4 + lr];
            float f3 = As[(r0 + 8) * APAD + kb + 4 + lr];
            if (tf) {
                f0 = fmaxf(fmaf(f0, s0, t0), 0.f);
                f1 = fmaxf(fmaf(f1, s0, t0), 0.f);
                f2 = fmaxf(fmaf(f2, s1, t1), 0.f);
                f3 = fmaxf(fmaf(f3, s1, t1), 0.f);
            }
            uint32_t ah[4], al[4];
            split_tf32(f0, ah[0], al[0]);
            split_tf32(f1, ah[1], al[1]);
            split_tf32(f2, ah[2], al[2]);
            split_tf32(f3, ah[3], al[3]);
#pragma unroll
            for (int nt = 0; nt < 4; nt++) {
                mma_tf32(acc[mt][nt], ah, bh[nt][0], bh[nt][1]);
                mma_tf32(acc[mt][nt], ah, bl[nt][0], bl[nt][1]);
                mma_tf32(acc[mt][nt], al, bh[nt][0], bh[nt][1]);
            }
        }
    }
}

__device__ __forceinline__ void gemm_epilogue(float acc[4][4][4], const float* bias,
                                              const float* add, float* C, int N, int M,
                                              int rowBase, int colBase,
                                              int wr, int wc, int lq, int lr) {
#pragma unroll
    for (int mt = 0; mt < 4; mt++) {
#pragma unroll
        for (int nt = 0; nt < 4; nt++) {
            int c = colBase + wc * 32 + nt * 8 + 2 * lr;
            float2 bv = make_float2(0.f, 0.f);
            if (bias) bv = *(const float2*)&bias[c];
            int r0 = rowBase + wr * 64 + mt * 16 + lq;
            int r1 = r0 + 8;
            if (r0 < N) {
                float2 o = make_float2(acc[mt][nt][0] + bv.x, acc[mt][nt][1] + bv.y);
                if (add) {
                    float2 av = *(const float2*)&add[(size_t)r0 * M + c];
                    o.x += av.x; o.y += av.y;
                }
                *(float2*)&C[(size_t)r0 * M + c] = o;
            }
            if (r1 < N) {
                float2 o = make_float2(acc[mt][nt][2] + bv.x, acc[mt][nt][3] + bv.y);
                if (add) {
                    float2 av = *(const float2*)&add[(size_t)r1 * M + c];
                    o.x += av.x; o.y += av.y;
                }
                *(float2*)&C[(size_t)r1 * M + c] = o;
            }
        }
    }
}

__device__ __forceinline__ void gemm_core(const float* A, const float* W,
                                          const float* bias, const float* add,
                                          const float* tS, const float* tT,
                                          float* C, int N, int K, int M,
                                          int rowBase, int colBase,
                                          float* Asm, float* Bsm) {
    int tid  = threadIdx.x;
    int lane = tid & 31;
    int w    = tid >> 5;
    int wr = w >> 2, wc = w & 3, lq = lane >> 2, lr = lane & 3;

    float acc[4][4][4];
#pragma unroll
    for (int mt = 0; mt < 4; mt++)
#pragma unroll
        for (int nt = 0; nt < 4; nt++)
#pragma unroll
            for (int i = 0; i < 4; i++) acc[mt][nt][i] = 0.f;

    gemm_stage(Asm, Bsm, A, W, N, K, M, rowBase, colBase, 0, tid);
    cp_commit();

    int nk = K / GBK;
    for (int t = 0; t < nk; t++) {
        int st  = t & 1;
        int nst = (t + 1) & 1;
        if (t + 1 < nk) {
            gemm_stage(Asm + nst * A_WORDS, Bsm + nst * B_WORDS,
                       A, W, N, K, M, rowBase, colBase, (t + 1) * GBK, tid);
            cp_commit();
            cp_wait<1>();
        } else {
            cp_wait<0>();
        }
        __syncthreads();
        gemm_mma(Asm + st * A_WORDS, Bsm + st * B_WORDS, acc,
                 wr, wc, lq, lr, tS, tT, t * GBK);
        __syncthreads();
    }
    gemm_epilogue(acc, bias, add, C, N, M, rowBase, colBase, wr, wc, lq, lr);
}

// generic GEMM (W1; W2 with transform/add)
__global__ __launch_bounds__(256, 2)
void gemm_kernel(const float* __restrict__ A, const float* __restrict__ W,
                 const float* __restrict__ bias, const float* __restrict__ add,
                 const float* __restrict__ tS, const float* __restrict__ tT,
                 float* __restrict__ C, int N, int K, int M) {
    __shared__ float Asm[2 * A_WORDS];
    __shared__ float Bsm[2 * B_WORDS];
    gemm_core(A, W, bias, add, tS, tT, C, N, K, M,
              blockIdx.x * GBM, blockIdx.y * GBN, Asm, Bsm);
}

// triple GEMM: shares A, computes xl/xr/xres. K=M=128. grid.y = 0..2 selects output.
__global__ __launch_bounds__(256, 2)
void gemm3_kernel(const float* __restrict__ A,
                  const float* __restrict__ W0, const float* __restrict__ W1,
                  const float* __restrict__ W2,
                  const float* __restrict__ b0, const float* __restrict__ b1,
                  const float* __restrict__ b2,
                  float* __restrict__ C0, float* __restrict__ C1,
                  float* __restrict__ C2) {
    __shared__ float Asm[2 * A_WORDS];
    __shared__ float Bsm[2 * B_WORDS];
    int sel = blockIdx.y;
    const float* W    = (sel == 0) ? W0 : (sel == 1) ? W1 : W2;
    const float* bias = (sel == 0) ? b0 : (sel == 1) ? b1 : b2;
    float* C          = (sel == 0) ? C0 : (sel == 1) ? C1 : C2;
    gemm_core(A, W, bias, nullptr, nullptr, nullptr, C, NN, DD, DD,
              blockIdx.x * GBM, 0, Asm, Bsm);
}

// ---------------- fused edge kernel ----------------
__device__ __forceinline__ float lky(float v) { return v > 0.f ? v : NEG * v; }

__global__ __launch_bounds__(256)
void edge_fused_kernel(const int* __restrict__ ei, const float* __restrict__ ea,
                       const float* __restrict__ We, const float* __restrict__ att) {
    constexpr int TE = 128;
    constexpr int EW = 16;
    __shared__ float ea_s[TE * EDD];
    __shared__ float We_s[EDD * DD];
    __shared__ float att_s[DD];

    int tid  = threadIdx.x;
    int lane = tid & 31;
    int w    = tid >> 5;
    int e0   = blockIdx.x * TE;

    {
        const float4* We4 = (const float4*)We;
        float4* Ws4 = (float4*)We_s;
#pragma unroll
        for (int i = 0; i < 4; i++) Ws4[tid + 256 * i] = We4[tid + 256 * i];
        const float4* ea4 = (const float4*)(ea + (size_t)e0 * EDD);
        float4* es4 = (float4*)ea_s;
#pragma unroll
        for (int i = 0; i < 4; i++) es4[tid + 256 * i] = ea4[tid + 256 * i];
        if (tid < DD) att_s[tid] = att[tid];
    }
    __syncthreads();

    float acc[EW][4];
#pragma unroll
    for (int i = 0; i < EW; i++)
#pragma unroll
        for (int j = 0; j < 4; j++) acc[i][j] = 0.f;

#pragma unroll
    for (int k = 0; k < EDD; k++) {
        float4 wv = *(float4*)&We_s[k * DD + lane * 4];
#pragma unroll
        for (int i = 0; i < EW; i++) {
            float a = ea_s[(w * EW + i) * EDD + k];
            acc[i][0] = fmaf(a, wv.x, acc[i][0]);
            acc[i][1] = fmaf(a, wv.y, acc[i][1]);
            acc[i][2] = fmaf(a, wv.z, acc[i][2]);
            acc[i][3] = fmaf(a, wv.w, acc[i][3]);
        }
    }

    float4 attv = *(float4*)&att_s[lane * 4];

#pragma unroll 4
    for (int i = 0; i < EW; i++) {
        int e = e0 + w * EW + i;
        int s = ei[e];
        int d = ei[NE + e];
        float4 xlv = *(const float4*)&g_xl[(size_t)s * DD + lane * 4];
        float4 xrv = *(const float4*)&g_xr[(size_t)d * DD + lane * 4];
        float mx = lky(acc[i][0] + xlv.x + xrv.x);
        float my = lky(acc[i][1] + xlv.y + xrv.y);
        float mz = lky(acc[i][2] + xlv.z + xrv.z);
        float mw = lky(acc[i][3] + xlv.w + xrv.w);
        float p = mx * attv.x + my * attv.y + mz * attv.z + mw * attv.w;
        p += __shfl_xor_sync(0xffffffffu, p, 1);
        p += __shfl_xor_sync(0xffffffffu, p, 2);
        int pos = g_pos[e];
        if ((lane & 3) == 0) g_alpha[(size_t)pos * NH + (lane >> 2)] = p;
    }
}

// ---------------- node aggregation ----------------
__global__ __launch_bounds__(256)
void node_agg_kernel() {
    int lane = threadIdx.x & 31;
    int n = blockIdx.x * 8 + (threadIdx.x >> 5);
    if (n >= NN) return;
    int h = lane >> 2;
    int beg = g_rowptr[n], end = g_rowptr[n + 1];
    float m = NEG_INF, den = 0.f;
    float4 acc = make_float4(0.f, 0.f, 0.f, 0.f);

    int j = beg;
    for (; j + 1 < end; j += 2) {
        float a0 = g_alpha[(size_t)j * NH + h];
        float a1 = g_alpha[(size_t)(j + 1) * NH + h];
        int   s0 = g_src[j];
        int   s1 = g_src[j + 1];
        float4 x0 = *(const float4*)&g_xl[(size_t)s0 * DD + lane * 4];
        float4 x1 = *(const float4*)&g_xl[(size_t)s1 * DD + lane * 4];

        float mn = fmaxf(m, a0);
        float corr = __expf(m - mn);
        float p = __expf(a0 - mn);
        den = den * corr + p;
        acc.x = acc.x * corr + p * x0.x;
        acc.y = acc.y * corr + p * x0.y;
        acc.z = acc.z * corr + p * x0.z;
        acc.w = acc.w * corr + p * x0.w;
        m = mn;

        mn = fmaxf(m, a1);
        corr = __expf(m - mn);
        p = __expf(a1 - mn);
        den = den * corr + p;
        acc.x = acc.x * corr + p * x1.x;
        acc.y = acc.y * corr + p * x1.y;
        acc.z = acc.z * corr + p * x1.z;
        acc.w = acc.w * corr + p * x1.w;
        m = mn;
    }
    for (; j < end; j++) {
        float a = g_alpha[(size_t)j * NH + h];
        int s = g_src[j];
        float4 xlv = *(const float4*)&g_xl[(size_t)s * DD + lane * 4];
        float mn = fmaxf(m, a);
        float corr = __expf(m - mn);
        float p = __expf(a - mn);
        den = den * corr + p;
        acc.x = acc.x * corr + p * xlv.x;
        acc.y = acc.y * corr + p * xlv.y;
        acc.z = acc.z * corr + p * xlv.z;
        acc.w = acc.w * corr + p * xlv.w;
        m = mn;
    }

    float inv = 1.f / (den + 1e-16f);
    float4 rv = *(const float4*)&g_xres[(size_t)n * DD + lane * 4];
    float4 o = make_float4(acc.x * inv + rv.x, acc.y * inv + rv.y,
                           acc.z * inv + rv.z, acc.w * inv + rv.w);
    *(float4*)&g_xtmp[(size_t)n * DD + lane * 4] = o;
}

// ---------------- BN column stats ----------------
__global__ void colstats_kernel() {
    int col = blockIdx.x * 128 + threadIdx.x;
    constexpr int CHUNK = (NN + 63) / 64;
    int r0 = blockIdx.y * CHUNK;
    int r1 = min(r0 + CHUNK, NN);
    float s = 0.f, q = 0.f;
    for (int r = r0; r < r1; r++) {
        float v = g_h[(size_t)r * HD + col];
        s += v;
        q += v * v;
    }
    atomicAdd(&g_bnstat[col], s);
    atomicAdd(&g_bnstat[HD + col], q);
}

__global__ void bn_final_kernel(const float* __restrict__ gamma, const float* __restrict__ beta) {
    int c = threadIdx.x;
    if (c >= HD) return;
    float invn = 1.f / (float)NN;
    float mu  = g_bnstat[c] * invn;
    float var = g_bnstat[HD + c] * invn - mu * mu;
    float istd = rsqrtf(var + EPSC);
    float s = gamma[c] * istd;
    g_bns[c] = s;
    g_bnt[c] = beta[c] - mu * s;
}

// ---------------- graph LayerNorm ----------------
__global__ __launch_bounds__(256)
void ln_stats_kernel(const int* __restrict__ nb) {
    int lane = threadIdx.x & 31;
    int n = blockIdx.x * 8 + (threadIdx.x >> 5);
    if (n >= NN) return;
    float4 v = *(const float4*)&g_x2[(size_t)n * DD + lane * 4];
    float s = v.x + v.y + v.z + v.w;
    float q = v.x * v.x + v.y * v.y + v.z * v.z + v.w * v.w;
#pragma unroll
    for (int off = 16; off > 0; off >>= 1) {
        s += __shfl_xor_sync(0xffffffffu, s, off);
        q += __shfl_xor_sync(0xffffffffu, q, off);
    }
    if (lane == 0) {
        int g = nb[n];
        atomicAdd(&g_gstat[g], s);
        atomicAdd(&g_gstat[GG + g], q);
    }
}

__global__ void ln_final_kernel() {
    int g = threadIdx.x;
    if (g >= GG) return;
    float cnt = fmaxf((float)g_gcnt[g], 1.f);
    float denom = cnt * (float)DD;
    float mean = g_gstat[g] / denom;
    float var  = g_gstat[GG + g] / denom - mean * mean;
    g_gmean[g] = mean;
    g_ginv[g]  = rsqrtf(var + EPSC);
}

__global__ void ln_apply_kernel(const int* __restrict__ nb,
                                const float* __restrict__ gamma,
                                const float* __restrict__ beta,
                                float* __restrict__ dst) {
    int idx = blockIdx.x * blockDim.x + threadIdx.x;
    if (idx >= NN * (DD / 4)) return;
    int n  = idx >> 5;
    int c4 = (idx & 31) * 4;
    int g  = nb[n];
    float mean = g_gmean[g];
    float ginv = g_ginv[g];
    float4 v  = *(const float4*)&g_x2[(size_t)n * DD + c4];
    float4 ga = *(const float4*)&gamma[c4];
    float4 be = *(const float4*)&beta[c4];
    float4 o;
    o.x = (v.x - mean) * ginv * ga.x + be.x;
    o.y = (v.y - mean) * ginv * ga.y + be.y;
    o.z = (v.z - mean) * ginv * ga.z + be.z;
    o.w = (v.w - mean) * ginv * ga.w + be.w;
    *(float4*)&dst[(size_t)n * DD + c4] = o;
}

// ---------------- host launch ----------------
extern "C" void kernel_launch(void* const* d_in, const int* in_sizes, int n_in,
                              void* d_out, int out_size) {
    const float* x    = (const float*)d_in[0];
    const int*   nb   = (const int*)  d_in[1];
    const int*   ei   = (const int*)  d_in[2];
    const float* ea   = (const float*)d_in[3];
    const float* Wl   = (const float*)d_in[4];
    const float* bl   = (const float*)d_in[5];
    const float* Wr   = (const float*)d_in[6];
    const float* br   = (const float*)d_in[7];
    const float* We   = (const float*)d_in[8];
    const float* att  = (const float*)d_in[9];
    const float* bias = (const float*)d_in[10];
    const float* Wres = (const float*)d_in[11];
    const float* W1   = (const float*)d_in[12];
    const float* b1   = (const float*)d_in[13];
    const float* bng  = (const float*)d_in[14];
    const float* bnb  = (const float*)d_in[15];
    const float* W2   = (const float*)d_in[16];
    const float* b2   = (const float*)d_in[17];
    const float* lng  = (const float*)d_in[18];
    const float* lnb  = (const float*)d_in[19];
    float* out = (float*)d_out;

    void* p;
    cudaGetSymbolAddress(&p, g_xl);   float* pxl   = (float*)p;
    cudaGetSymbolAddress(&p, g_xr);   float* pxr   = (float*)p;
    cudaGetSymbolAddress(&p, g_xres); float* pxres = (float*)p;
    cudaGetSymbolAddress(&p, g_xtmp); float* pxtmp = (float*)p;
    cudaGetSymbolAddress(&p, g_x2);   float* px2   = (float*)p;
    cudaGetSymbolAddress(&p, g_xcur); float* pxcur = (float*)p;
    cudaGetSymbolAddress(&p, g_h);    float* ph    = (float*)p;
    cudaGetSymbolAddress(&p, g_bns);  float* pbns  = (float*)p;
    cudaGetSymbolAddress(&p, g_bnt);  float* pbnt  = (float*)p;

    const int GR = (NN + 127) / 128;   // 391

    // launches 1-3 (CSR prologue); layer-0 gemm3 is launch #4 for the ncu window
    zero_init_kernel<<<(NN + 255) / 256, 256>>>();
    hist_kernel<<<(NE + 255) / 256, 256>>>(ei, nb);
    scan_kernel<<<1, 1024>>>();

    const float* xin = x;
    for (int l = 0; l < 2; l++) {
        gemm3_kernel<<<dim3(GR, 3), 256>>>(xin,
            Wl + (size_t)l * DD * DD, Wr + (size_t)l * DD * DD, Wres + (size_t)l * DD * DD,
            bl + l * DD, br + l * DD, bias + l * DD,
            pxl, pxr, pxres);
        if (l == 0) scatter_kernel<<<(NE + 255) / 256, 256>>>(ei);
        zero_stats_kernel<<<2, 1024>>>();

        edge_fused_kernel<<<NE / 128, 256>>>(ei, ea, We + (size_t)l * EDD * DD, att + l * DD);
        node_agg_kernel<<<(NN + 7) / 8, 256>>>();

        gemm_kernel<<<dim3(GR, 4), 256>>>(pxtmp, W1 + (size_t)l * DD * HD, b1 + l * HD,
                                          nullptr, nullptr, nullptr, ph, NN, DD, HD);
        colstats_kernel<<<dim3(4, 64), 128>>>();
        bn_final_kernel<<<1, 512>>>(bng + l * HD, bnb + l * HD);
        gemm_kernel<<<dim3(GR, 1), 256>>>(ph, W2 + (size_t)l * HD * DD, b2 + l * DD,
                                          pxtmp, pbns, pbnt, px2, NN, HD, DD);

        ln_stats_kernel<<<(NN + 7) / 8, 256>>>(nb);
        ln_final_kernel<<<1, 64>>>();
        float* dst = (l == 1) ? out : pxcur;
        ln_apply_kernel<<<(NN * (DD / 4) + 255) / 256, 256>>>(nb, lng + l * DD, lnb + l * DD, dst);

        xin = pxcur;
    }
}

// round 11
// speedup vs baseline: 1.1982x; 1.0018x over previous
#include <cuda_runtime.h>
#include <cstdint>
#include <cstdio>

// ---------------- problem constants ----------------
constexpr int NN  = 50000;   // nodes
constexpr int NE  = 800000;  // edges
constexpr int DD  = 128;     // channels
constexpr int NH  = 8;       // heads
constexpr int EDD = 32;      // edge_dim
constexpr int HD  = 512;     // mlp hidden
constexpr int GG  = 64;      // graphs
constexpr float NEG  = 0.2f;
constexpr float EPSC = 1e-5f;

#define NEG_INF (__int_as_float(0xff800000u))

// ---------------- device scratch ----------------
__device__ float g_xl  [NN * DD];
__device__ float g_xr  [NN * DD];
__device__ float g_xres[NN * DD];
__device__ float g_xtmp[NN * DD];
__device__ float g_x2  [NN * DD];
__device__ float g_xcur[NN * DD];
__device__ float g_h   [(size_t)NN * HD];
__device__ float g_alpha[(size_t)NE * NH];       // CSR-ordered: [pos][head]

__device__ int g_deg   [NN];
__device__ int g_rowptr[NN + 1];
__device__ int g_wp    [NN];
__device__ int g_pos   [NE];
__device__ int g_src   [NE];
__device__ int g_gcnt  [GG];

__device__ float g_bnstat[2 * HD];
__device__ float g_bns[HD];
__device__ float g_bnt[HD];
__device__ float g_gstat[2 * GG];
__device__ float g_gmean[GG];
__device__ float g_ginv [GG];

// ---------------- setup kernels ----------------
__global__ void zero_init_kernel() {
    int i = blockIdx.x * blockDim.x + threadIdx.x;
    if (i < NN) g_deg[i] = 0;
    if (i < GG) g_gcnt[i] = 0;
}

__global__ void hist_kernel(const int* __restrict__ ei, const int* __restrict__ nb) {
    int i = blockIdx.x * blockDim.x + threadIdx.x;
    if (i < NE) atomicAdd(&g_deg[ei[NE + i]], 1);
    if (i < NN) atomicAdd(&g_gcnt[nb[i]], 1);
}

__global__ void scan_kernel() {
    __shared__ int part[1024];
    constexpr int CHUNK = (NN + 1023) / 1024;
    int t = threadIdx.x;
    int base = t * CHUNK;
    int s = 0;
    for (int i = 0; i < CHUNK; i++) {
        int idx = base + i;
        if (idx < NN) s += g_deg[idx];
    }
    part[t] = s;
    __syncthreads();
    for (int off = 1; off < 1024; off <<= 1) {
        int v = (t >= off) ? part[t - off] : 0;
        __syncthreads();
        part[t] += v;
        __syncthreads();
    }
    int run = (t == 0) ? 0 : part[t - 1];
    for (int i = 0; i < CHUNK; i++) {
        int idx = base + i;
        if (idx < NN) {
            g_rowptr[idx] = run;
            g_wp[idx] = run;
            run += g_deg[idx];
        }
    }
    if (t == 1023) g_rowptr[NN] = part[1023];
}

__global__ void scatter_kernel(const int* __restrict__ ei) {
    int e = blockIdx.x * blockDim.x + threadIdx.x;
    if (e >= NE) return;
    int s = ei[e];
    int d = ei[NE + e];
    int p = atomicAdd(&g_wp[d], 1);
    g_pos[e] = p;
    g_src[p] = s;
}

__global__ void zero_stats_kernel() {
    int i = blockIdx.x * blockDim.x + threadIdx.x;
    if (i < 2 * HD) g_bnstat[i] = 0.f;
    if (i < 2 * GG) g_gstat[i] = 0.f;
}

// ---------------- split-TF32 + cp.async helpers ----------------
__device__ __forceinline__ uint32_t to_tf32(float f) {
    uint32_t r;
    asm("cvt.rna.tf32.f32 %0, %1;" : "=r"(r) : "f"(f));
    return r;
}

__device__ __forceinline__ void split_tf32(float f, uint32_t& hi, uint32_t& lo) {
    hi = to_tf32(f);
    lo = to_tf32(f - __uint_as_float(hi));
}

__device__ __forceinline__ void mma_tf32(float c[4], const uint32_t a[4],
                                         uint32_t b0, uint32_t b1) {
    asm volatile(
        "mma.sync.aligned.m16n8k8.row.col.f32.tf32.tf32.f32 "
        "{%0,%1,%2,%3},{%4,%5,%6,%7},{%8,%9},{%0,%1,%2,%3};"
        : "+f"(c[0]), "+f"(c[1]), "+f"(c[2]), "+f"(c[3])
        : "r"(a[0]), "r"(a[1]), "r"(a[2]), "r"(a[3]), "r"(b0), "r"(b1));
}

__device__ __forceinline__ void cp16(uint32_t dst, const void* src, bool valid) {
    int sz = valid ? 16 : 0;
    asm volatile("cp.async.ca.shared.global [%0], [%1], 16, %2;"
                 :: "r"(dst), "l"(src), "r"(sz));
}
__device__ __forceinline__ void cp_commit() {
    asm volatile("cp.async.commit_group;");
}
template <int NW>
__device__ __forceinline__ void cp_wait() {
    asm volatile("cp.async.wait_group %0;" :: "n"(NW));
}

// ---------------- TF32 split GEMM, cp.async 3-stage pipeline ----------------
// BM=128, BN=128, BK=16. 256 threads = 8 warps; warp tile 64(M) x 32(N).
// A smem: As[row][20] fp32  (frag banks 20*lq+lr: conflict-free)
// B smem: Bs[k][136] fp32, k-major (frag banks 8*lr+lq: conflict-free)
constexpr int GBM = 128, GBN = 128, GBK = 16;
constexpr int APAD = 20;    // A row stride (words)
constexpr int BSTR = 136;   // B k-row stride (words)
constexpr int A_WORDS = GBM * APAD;           // 2560
constexpr int B_WORDS = GBK * BSTR;           // 2176
constexpr int STAGE_WORDS = A_WORDS + B_WORDS; // 4736
constexpr int NSTAGE = 3;
constexpr int GEMM_SMEM_BYTES = NSTAGE * STAGE_WORDS * 4;  // 56832

// issue cp.async for one k-tile into stage buffer (A at +0, B at +A_WORDS)
__device__ __forceinline__ void gemm_stage(float* stage,
                                           const float* A, const float* W,
                                           int N, int K, int M,
                                           int rowBase, int colBase, int k0, int tid) {
    float* As = stage;
    float* Bs = stage + A_WORDS;
    int c0   = tid * 2;
    int arow = c0 >> 2;
    int akq  = (c0 & 3) * 4;
    int grow = rowBase + arow;
    bool av  = grow < N;
    const float* asrc = &A[(size_t)grow * K + k0 + akq];
    uint32_t adst = (uint32_t)__cvta_generic_to_shared(&As[arow * APAD + akq]);
    cp16(adst, asrc, av);
    cp16(adst + 16, asrc + 4, av);
    int bk = tid >> 5;
    int bn = (tid & 31) * 4;
    const float* bsrc0 = &W[(size_t)(k0 + bk) * M + colBase + bn];
    const float* bsrc1 = &W[(size_t)(k0 + bk + 8) * M + colBase + bn];
    cp16((uint32_t)__cvta_generic_to_shared(&Bs[bk * BSTR + bn]), bsrc0, true);
    cp16((uint32_t)__cvta_generic_to_shared(&Bs[(bk + 8) * BSTR + bn]), bsrc1, true);
}

__device__ __forceinline__ void gemm_mma(const float* stage,
                                         float acc[4][4][4],
                                         int wr, int wc, int lq, int lr,
                                         const float* tS, const float* tT, int k0) {
    const float* As = stage;
    const float* Bs = stage + A_WORDS;
#pragma unroll
    for (int ks = 0; ks < 2; ks++) {
        int kb = ks * 8;
        uint32_t bh[4][2], bl[4][2];
#pragma unroll
        for (int nt = 0; nt < 4; nt++) {
            int n0 = wc * 32 + nt * 8 + lq;
            split_tf32(Bs[(kb + lr) * BSTR + n0], bh[nt][0], bl[nt][0]);
            split_tf32(Bs[(kb + 4 + lr) * BSTR + n0], bh[nt][1], bl[nt][1]);
        }
        float s0 = 0.f, t0 = 0.f, s1 = 0.f, t1 = 0.f;
        bool tf = (tS != nullptr);
        if (tf) {
            s0 = tS[k0 + kb + lr];     t0 = tT[k0 + kb + lr];
            s1 = tS[k0 + kb + 4 + lr]; t1 = tT[k0 + kb + 4 + lr];
        }
#pragma unroll
        for (int mt = 0; mt < 4; mt++) {
            int r0 = wr * 64 + mt * 16 + lq;
            float f0 = As[r0 * APAD + kb + lr];
            float f1 = As[(r0 + 8) * APAD + kb + lr];
            float f2 = As[r0 * APAD + kb + 4 + lr];
            float f3 = As[(r0 + 8) * APAD + kb + 4 + lr];
            if (tf) {
                f0 = fmaxf(fmaf(f0, s0, t0), 0.f);
                f1 = fmaxf(fmaf(f1, s0, t0), 0.f);
                f2 = fmaxf(fmaf(f2, s1, t1), 0.f);
                f3 = fmaxf(fmaf(f3, s1, t1), 0.f);
            }
            uint32_t ah[4], al[4];
            split_tf32(f0, ah[0], al[0]);
            split_tf32(f1, ah[1], al[1]);
            split_tf32(f2, ah[2], al[2]);
            split_tf32(f3, ah[3], al[3]);
#pragma unroll
            for (int nt = 0; nt < 4; nt++) {
                mma_tf32(acc[mt][nt], ah, bh[nt][0], bh[nt][1]);
                mma_tf32(acc[mt][nt], ah, bl[nt][0], bl[nt][1]);
                mma_tf32(acc[mt][nt], al, bh[nt][0], bh[nt][1]);
            }
        }
    }
}

__device__ __forceinline__ void gemm_epilogue(float acc[4][4][4], const float* bias,
                                              const float* add, float* C, int N, int M,
                                              int rowBase, int colBase,
                                              int wr, int wc, int lq, int lr) {
#pragma unroll
    for (int mt = 0; mt < 4; mt++) {
#pragma unroll
        for (int nt = 0; nt < 4; nt++) {
            int c = colBase + wc * 32 + nt * 8 + 2 * lr;
            float2 bv = make_float2(0.f, 0.f);
            if (bias) bv = *(const float2*)&bias[c];
            int r0 = rowBase + wr * 64 + mt * 16 + lq;
            int r1 = r0 + 8;
            if (r0 < N) {
                float2 o = make_float2(acc[mt][nt][0] + bv.x, acc[mt][nt][1] + bv.y);
                if (add) {
                    float2 av = *(const float2*)&add[(size_t)r0 * M + c];
                    o.x += av.x; o.y += av.y;
                }
                *(float2*)&C[(size_t)r0 * M + c] = o;
            }
            if (r1 < N) {
                float2 o = make_float2(acc[mt][nt][2] + bv.x, acc[mt][nt][3] + bv.y);
                if (add) {
                    float2 av = *(const float2*)&add[(size_t)r1 * M + c];
                    o.x += av.x; o.y += av.y;
                }
                *(float2*)&C[(size_t)r1 * M + c] = o;
            }
        }
    }
}

// 3-stage mainloop: per iteration -> wait<1>, ONE sync, mma(t), stage(t+2), commit.
// stage(t+2) writes buffer (t+2)%3 == (t-1)%3; its readers (mma(t-1)) are fenced
// by this iteration's sync. wait<1> completes exactly group t.
__device__ __forceinline__ void gemm_core(const float* A, const float* W,
                                          const float* bias, const float* add,
                                          const float* tS, const float* tT,
                                          float* C, int N, int K, int M,
                                          int rowBase, int colBase, float* sm) {
    int tid  = threadIdx.x;
    int lane = tid & 31;
    int w    = tid >> 5;
    int wr = w >> 2, wc = w & 3, lq = lane >> 2, lr = lane & 3;

    float acc[4][4][4];
#pragma unroll
    for (int mt = 0; mt < 4; mt++)
#pragma unroll
        for (int nt = 0; nt < 4; nt++)
#pragma unroll
            for (int i = 0; i < 4; i++) acc[mt][nt][i] = 0.f;

    int nk = K / GBK;
    gemm_stage(sm, A, W, N, K, M, rowBase, colBase, 0, tid);
    cp_commit();
    gemm_stage(sm + STAGE_WORDS, A, W, N, K, M, rowBase, colBase, GBK, tid);
    cp_commit();

    for (int t = 0; t < nk; t++) {
        cp_wait<1>();
        __syncthreads();
        gemm_mma(sm + (t % 3) * STAGE_WORDS, acc, wr, wc, lq, lr, tS, tT, t * GBK);
        if (t + 2 < nk)
            gemm_stage(sm + ((t + 2) % 3) * STAGE_WORDS, A, W, N, K, M,
                       rowBase, colBase, (t + 2) * GBK, tid);
        cp_commit();
    }
    __syncthreads();
    gemm_epilogue(acc, bias, add, C, N, M, rowBase, colBase, wr, wc, lq, lr);
}

// generic GEMM (W1; W2 with transform/add)
__global__ __launch_bounds__(256, 2)
void gemm_kernel(const float* __restrict__ A, const float* __restrict__ W,
                 const float* __restrict__ bias, const float* __restrict__ add,
                 const float* __restrict__ tS, const float* __restrict__ tT,
                 float* __restrict__ C, int N, int K, int M) {
    extern __shared__ float dynsm[];
    gemm_core(A, W, bias, add, tS, tT, C, N, K, M,
              blockIdx.x * GBM, blockIdx.y * GBN, dynsm);
}

// triple GEMM: shares A, computes xl/xr/xres. K=M=128. grid.y = 0..2 selects output.
__global__ __launch_bounds__(256, 2)
void gemm3_kernel(const float* __restrict__ A,
                  const float* __restrict__ W0, const float* __restrict__ W1,
                  const float* __restrict__ W2,
                  const float* __restrict__ b0, const float* __restrict__ b1,
                  const float* __restrict__ b2,
                  float* __restrict__ C0, float* __restrict__ C1,
                  float* __restrict__ C2) {
    extern __shared__ float dynsm[];
    int sel = blockIdx.y;
    const float* W    = (sel == 0) ? W0 : (sel == 1) ? W1 : W2;
    const float* bias = (sel == 0) ? b0 : (sel == 1) ? b1 : b2;
    float* C          = (sel == 0) ? C0 : (sel == 1) ? C1 : C2;
    gemm_core(A, W, bias, nullptr, nullptr, nullptr, C, NN, DD, DD,
              blockIdx.x * GBM, 0, dynsm);
}

// ---------------- fused edge kernel ----------------
__device__ __forceinline__ float lky(float v) { return v > 0.f ? v : NEG * v; }

__global__ __launch_bounds__(256)
void edge_fused_kernel(const int* __restrict__ ei, const float* __restrict__ ea,
                       const float* __restrict__ We, const float* __restrict__ att) {
    constexpr int TE = 128;
    constexpr int EW = 16;
    __shared__ float ea_s[TE * EDD];
    __shared__ float We_s[EDD * DD];
    __shared__ float att_s[DD];

    int tid  = threadIdx.x;
    int lane = tid & 31;
    int w    = tid >> 5;
    int e0   = blockIdx.x * TE;

    {
        const float4* We4 = (const float4*)We;
        float4* Ws4 = (float4*)We_s;
#pragma unroll
        for (int i = 0; i < 4; i++) Ws4[tid + 256 * i] = We4[tid + 256 * i];
        const float4* ea4 = (const float4*)(ea + (size_t)e0 * EDD);
        float4* es4 = (float4*)ea_s;
#pragma unroll
        for (int i = 0; i < 4; i++) es4[tid + 256 * i] = ea4[tid + 256 * i];
        if (tid < DD) att_s[tid] = att[tid];
    }
    __syncthreads();

    float acc[EW][4];
#pragma unroll
    for (int i = 0; i < EW; i++)
#pragma unroll
        for (int j = 0; j < 4; j++) acc[i][j] = 0.f;

#pragma unroll
    for (int k = 0; k < EDD; k++) {
        float4 wv = *(float4*)&We_s[k * DD + lane * 4];
#pragma unroll
        for (int i = 0; i < EW; i++) {
            float a = ea_s[(w * EW + i) * EDD + k];
            acc[i][0] = fmaf(a, wv.x, acc[i][0]);
            acc[i][1] = fmaf(a, wv.y, acc[i][1]);
            acc[i][2] = fmaf(a, wv.z, acc[i][2]);
            acc[i][3] = fmaf(a, wv.w, acc[i][3]);
        }
    }

    float4 attv = *(float4*)&att_s[lane * 4];

#pragma unroll 4
    for (int i = 0; i < EW; i++) {
        int e = e0 + w * EW + i;
        int s = ei[e];
        int d = ei[NE + e];
        float4 xlv = *(const float4*)&g_xl[(size_t)s * DD + lane * 4];
        float4 xrv = *(const float4*)&g_xr[(size_t)d * DD + lane * 4];
        float mx = lky(acc[i][0] + xlv.x + xrv.x);
        float my = lky(acc[i][1] + xlv.y + xrv.y);
        float mz = lky(acc[i][2] + xlv.z + xrv.z);
        float mw = lky(acc[i][3] + xlv.w + xrv.w);
        float p = mx * attv.x + my * attv.y + mz * attv.z + mw * attv.w;
        p += __shfl_xor_sync(0xffffffffu, p, 1);
        p += __shfl_xor_sync(0xffffffffu, p, 2);
        int pos = g_pos[e];
        if ((lane & 3) == 0) g_alpha[(size_t)pos * NH + (lane >> 2)] = p;
    }
}

// ---------------- node aggregation ----------------
__global__ __launch_bounds__(256)
void node_agg_kernel() {
    int lane = threadIdx.x & 31;
    int n = blockIdx.x * 8 + (threadIdx.x >> 5);
    if (n >= NN) return;
    int h = lane >> 2;
    int beg = g_rowptr[n], end = g_rowptr[n + 1];
    float m = NEG_INF, den = 0.f;
    float4 acc = make_float4(0.f, 0.f, 0.f, 0.f);

    int j = beg;
    for (; j + 1 < end; j += 2) {
        float a0 = g_alpha[(size_t)j * NH + h];
        float a1 = g_alpha[(size_t)(j + 1) * NH + h];
        int   s0 = g_src[j];
        int   s1 = g_src[j + 1];
        float4 x0 = *(const float4*)&g_xl[(size_t)s0 * DD + lane * 4];
        float4 x1 = *(const float4*)&g_xl[(size_t)s1 * DD + lane * 4];

        float mn = fmaxf(m, a0);
        float corr = __expf(m - mn);
        float p = __expf(a0 - mn);
        den = den * corr + p;
        acc.x = acc.x * corr + p * x0.x;
        acc.y = acc.y * corr + p * x0.y;
        acc.z = acc.z * corr + p * x0.z;
        acc.w = acc.w * corr + p * x0.w;
        m = mn;

        mn = fmaxf(m, a1);
        corr = __expf(m - mn);
        p = __expf(a1 - mn);
        den = den * corr + p;
        acc.x = acc.x * corr + p * x1.x;
        acc.y = acc.y * corr + p * x1.y;
        acc.z = acc.z * corr + p * x1.z;
        acc.w = acc.w * corr + p * x1.w;
        m = mn;
    }
    for (; j < end; j++) {
        float a = g_alpha[(size_t)j * NH + h];
        int s = g_src[j];
        float4 xlv = *(const float4*)&g_xl[(size_t)s * DD + lane * 4];
        float mn = fmaxf(m, a);
        float corr = __expf(m - mn);
        float p = __expf(a - mn);
        den = den * corr + p;
        acc.x = acc.x * corr + p * xlv.x;
        acc.y = acc.y * corr + p * xlv.y;
        acc.z = acc.z * corr + p * xlv.z;
        acc.w = acc.w * corr + p * xlv.w;
        m = mn;
    }

    float inv = 1.f / (den + 1e-16f);
    float4 rv = *(const float4*)&g_xres[(size_t)n * DD + lane * 4];
    float4 o = make_float4(acc.x * inv + rv.x, acc.y * inv + rv.y,
                           acc.z * inv + rv.z, acc.w * inv + rv.w);
    *(float4*)&g_xtmp[(size_t)n * DD + lane * 4] = o;
}

// ---------------- BN column stats ----------------
__global__ void colstats_kernel() {
    int col = blockIdx.x * 128 + threadIdx.x;
    constexpr int CHUNK = (NN + 63) / 64;
    int r0 = blockIdx.y * CHUNK;
    int r1 = min(r0 + CHUNK, NN);
    float s = 0.f, q = 0.f;
    for (int r = r0; r < r1; r++) {
        float v = g_h[(size_t)r * HD + col];
        s += v;
        q += v * v;
    }
    atomicAdd(&g_bnstat[col], s);
    atomicAdd(&g_bnstat[HD + col], q);
}

__global__ void bn_final_kernel(const float* __restrict__ gamma, const float* __restrict__ beta) {
    int c = threadIdx.x;
    if (c >= HD) return;
    float invn = 1.f / (float)NN;
    float mu  = g_bnstat[c] * invn;
    float var = g_bnstat[HD + c] * invn - mu * mu;
    float istd = rsqrtf(var + EPSC);
    float s = gamma[c] * istd;
    g_bns[c] = s;
    g_bnt[c] = beta[c] - mu * s;
}

// ---------------- graph LayerNorm ----------------
__global__ __launch_bounds__(256)
void ln_stats_kernel(const int* __restrict__ nb) {
    int lane = threadIdx.x & 31;
    int n = blockIdx.x * 8 + (threadIdx.x >> 5);
    if (n >= NN) return;
    float4 v = *(const float4*)&g_x2[(size_t)n * DD + lane * 4];
    float s = v.x + v.y + v.z + v.w;
    float q = v.x * v.x + v.y * v.y + v.z * v.z + v.w * v.w;
#pragma unroll
    for (int off = 16; off > 0; off >>= 1) {
        s += __shfl_xor_sync(0xffffffffu, s, off);
        q += __shfl_xor_sync(0xffffffffu, q, off);
    }
    if (lane == 0) {
        int g = nb[n];
        atomicAdd(&g_gstat[g], s);
        atomicAdd(&g_gstat[GG + g], q);
    }
}

__global__ void ln_final_kernel() {
    int g = threadIdx.x;
    if (g >= GG) return;
    float cnt = fmaxf((float)g_gcnt[g], 1.f);
    float denom = cnt * (float)DD;
    float mean = g_gstat[g] / denom;
    float var  = g_gstat[GG + g] / denom - mean * mean;
    g_gmean[g] = mean;
    g_ginv[g]  = rsqrtf(var + EPSC);
}

__global__ void ln_apply_kernel(const int* __restrict__ nb,
                                const float* __restrict__ gamma,
                                const float* __restrict__ beta,
                                float* __restrict__ dst) {
    int idx = blockIdx.x * blockDim.x + threadIdx.x;
    if (idx >= NN * (DD / 4)) return;
    int n  = idx >> 5;
    int c4 = (idx & 31) * 4;
    int g  = nb[n];
    float mean = g_gmean[g];
    float ginv = g_ginv[g];
    float4 v  = *(const float4*)&g_x2[(size_t)n * DD + c4];
    float4 ga = *(const float4*)&gamma[c4];
    float4 be = *(const float4*)&beta[c4];
    float4 o;
    o.x = (v.x - mean) * ginv * ga.x + be.x;
    o.y = (v.y - mean) * ginv * ga.y + be.y;
    o.z = (v.z - mean) * ginv * ga.z + be.z;
    o.w = (v.w - mean) * ginv * ga.w + be.w;
    *(float4*)&dst[(size_t)n * DD + c4] = o;
}

// ---------------- host launch ----------------
extern "C" void kernel_launch(void* const* d_in, const int* in_sizes, int n_in,
                              void* d_out, int out_size) {
    const float* x    = (const float*)d_in[0];
    const int*   nb   = (const int*)  d_in[1];
    const int*   ei   = (const int*)  d_in[2];
    const float* ea   = (const float*)d_in[3];
    const float* Wl   = (const float*)d_in[4];
    const float* bl   = (const float*)d_in[5];
    const float* Wr   = (const float*)d_in[6];
    const float* br   = (const float*)d_in[7];
    const float* We   = (const float*)d_in[8];
    const float* att  = (const float*)d_in[9];
    const float* bias = (const float*)d_in[10];
    const float* Wres = (const float*)d_in[11];
    const float* W1   = (const float*)d_in[12];
    const float* b1   = (const float*)d_in[13];
    const float* bng  = (const float*)d_in[14];
    const float* bnb  = (const float*)d_in[15];
    const float* W2   = (const float*)d_in[16];
    const float* b2   = (const float*)d_in[17];
    const float* lng  = (const float*)d_in[18];
    const float* lnb  = (const float*)d_in[19];
    float* out = (float*)d_out;

    void* p;
    cudaGetSymbolAddress(&p, g_xl);   float* pxl   = (float*)p;
    cudaGetSymbolAddress(&p, g_xr);   float* pxr   = (float*)p;
    cudaGetSymbolAddress(&p, g_xres); float* pxres = (float*)p;
    cudaGetSymbolAddress(&p, g_xtmp); float* pxtmp = (float*)p;
    cudaGetSymbolAddress(&p, g_x2);   float* px2   = (float*)p;
    cudaGetSymbolAddress(&p, g_xcur); float* pxcur = (float*)p;
    cudaGetSymbolAddress(&p, g_h);    float* ph    = (float*)p;
    cudaGetSymbolAddress(&p, g_bns);  float* pbns  = (float*)p;
    cudaGetSymbolAddress(&p, g_bnt);  float* pbnt  = (float*)p;

    // allow >48KB dynamic smem (host-side attribute; capture-legal, no alloc)
    cudaFuncSetAttribute(gemm_kernel,  cudaFuncAttributeMaxDynamicSharedMemorySize, GEMM_SMEM_BYTES);
    cudaFuncSetAttribute(gemm3_kernel, cudaFuncAttributeMaxDynamicSharedMemorySize, GEMM_SMEM_BYTES);

    const int GR = (NN + 127) / 128;   // 391

    // launches 1-3 (CSR prologue); layer-0 gemm3 is launch #4 for the ncu window
    zero_init_kernel<<<(NN + 255) / 256, 256>>>();
    hist_kernel<<<(NE + 255) / 256, 256>>>(ei, nb);
    scan_kernel<<<1, 1024>>>();

    const float* xin = x;
    for (int l = 0; l < 2; l++) {
        gemm3_kernel<<<dim3(GR, 3), 256, GEMM_SMEM_BYTES>>>(xin,
            Wl + (size_t)l * DD * DD, Wr + (size_t)l * DD * DD, Wres + (size_t)l * DD * DD,
            bl + l * DD, br + l * DD, bias + l * DD,
            pxl, pxr, pxres);
        if (l == 0) scatter_kernel<<<(NE + 255) / 256, 256>>>(ei);
        zero_stats_kernel<<<2, 1024>>>();

        edge_fused_kernel<<<NE / 128, 256>>>(ei, ea, We + (size_t)l * EDD * DD, att + l * DD);
        node_agg_kernel<<<(NN + 7) / 8, 256>>>();

        gemm_kernel<<<dim3(GR, 4), 256, GEMM_SMEM_BYTES>>>(pxtmp, W1 + (size_t)l * DD * HD, b1 + l * HD,
                                          nullptr, nullptr, nullptr, ph, NN, DD, HD);
        colstats_kernel<<<dim3(4, 64), 128>>>();
        bn_final_kernel<<<1, 512>>>(bng + l * HD, bnb + l * HD);
        gemm_kernel<<<dim3(GR, 1), 256, GEMM_SMEM_BYTES>>>(ph, W2 + (size_t)l * HD * DD, b2 + l * DD,
                                          pxtmp, pbns, pbnt, px2, NN, HD, DD);

        ln_stats_kernel<<<(NN + 7) / 8, 256>>>(nb);
        ln_final_kernel<<<1, 64>>>();
        float* dst = (l == 1) ? out : pxcur;
        ln_apply_kernel<<<(NN * (DD / 4) + 255) / 256, 256>>>(nb, lng + l * DD, lnb + l * DD, dst);

        xin = pxcur;
    }
}

// round 12
// speedup vs baseline: 1.3340x; 1.1134x over previous
#include <cuda_runtime.h>
#include <cuda_bf16.h>
#include <cstdint>
#include <cstdio>

// ---------------- problem constants ----------------
constexpr int NN  = 50000;   // nodes
constexpr int NE  = 800000;  // edges
constexpr int DD  = 128;     // channels
constexpr int NH  = 8;       // heads
constexpr int EDD = 32;      // edge_dim
constexpr int HD  = 512;     // mlp hidden
constexpr int GG  = 64;      // graphs
constexpr float NEG  = 0.2f;
constexpr float EPSC = 1e-5f;

#define NEG_INF (__int_as_float(0xff800000u))

// ---------------- device scratch ----------------
__device__ float g_xl  [NN * DD];
__device__ float g_xr  [NN * DD];
__device__ float g_xres[NN * DD];
__device__ float g_xtmp[NN * DD];
__device__ float g_x2  [NN * DD];
__device__ float g_xcur[NN * DD];
__device__ float g_h   [(size_t)NN * HD];
__device__ float g_alpha[(size_t)NE * NH];       // CSR-ordered: [pos][head]

__device__ int g_deg   [NN];
__device__ int g_rowptr[NN + 1];
__device__ int g_wp    [NN];
__device__ int g_pos   [NE];
__device__ int g_src   [NE];
__device__ int g_gcnt  [GG];

__device__ float g_bnstat[2 * HD];
__device__ float g_bns[HD];
__device__ float g_bnt[HD];
__device__ float g_gstat[2 * GG];
__device__ float g_gmean[GG];
__device__ float g_ginv [GG];

// ---------------- setup kernels ----------------
__global__ void zero_init_kernel() {
    int i = blockIdx.x * blockDim.x + threadIdx.x;
    if (i < NN) g_deg[i] = 0;
    if (i < GG) g_gcnt[i] = 0;
}

__global__ void hist_kernel(const int* __restrict__ ei, const int* __restrict__ nb) {
    int i = blockIdx.x * blockDim.x + threadIdx.x;
    if (i < NE) atomicAdd(&g_deg[ei[NE + i]], 1);
    if (i < NN) atomicAdd(&g_gcnt[nb[i]], 1);
}

__global__ void scan_kernel() {
    __shared__ int part[1024];
    constexpr int CHUNK = (NN + 1023) / 1024;
    int t = threadIdx.x;
    int base = t * CHUNK;
    int s = 0;
    for (int i = 0; i < CHUNK; i++) {
        int idx = base + i;
        if (idx < NN) s += g_deg[idx];
    }
    part[t] = s;
    __syncthreads();
    for (int off = 1; off < 1024; off <<= 1) {
        int v = (t >= off) ? part[t - off] : 0;
        __syncthreads();
        part[t] += v;
        __syncthreads();
    }
    int run = (t == 0) ? 0 : part[t - 1];
    for (int i = 0; i < CHUNK; i++) {
        int idx = base + i;
        if (idx < NN) {
            g_rowptr[idx] = run;
            g_wp[idx] = run;
            run += g_deg[idx];
        }
    }
    if (t == 1023) g_rowptr[NN] = part[1023];
}

__global__ void scatter_kernel(const int* __restrict__ ei) {
    int e = blockIdx.x * blockDim.x + threadIdx.x;
    if (e >= NE) return;
    int s = ei[e];
    int d = ei[NE + e];
    int p = atomicAdd(&g_wp[d], 1);
    g_pos[e] = p;
    g_src[p] = s;
}

__global__ void zero_stats_kernel() {
    int i = blockIdx.x * blockDim.x + threadIdx.x;
    if (i < 2 * HD) g_bnstat[i] = 0.f;
    if (i < 2 * GG) g_gstat[i] = 0.f;
}

// ---------------- split-BF16 + cp.async helpers ----------------
// pack (f0,f1) into bf16x2 hi and residual lo: f = hi + lo + O(2^-18)
__device__ __forceinline__ void split_bf16x2(float f0, float f1,
                                             uint32_t& hi, uint32_t& lo) {
    __nv_bfloat162 h = __floats2bfloat162_rn(f0, f1);
    float r0 = f0 - __bfloat162float(h.x);
    float r1 = f1 - __bfloat162float(h.y);
    __nv_bfloat162 l = __floats2bfloat162_rn(r0, r1);
    hi = *(uint32_t*)&h;
    lo = *(uint32_t*)&l;
}

__device__ __forceinline__ void mma_bf16(float c[4], const uint32_t a[4],
                                         uint32_t b0, uint32_t b1) {
    asm volatile(
        "mma.sync.aligned.m16n8k16.row.col.f32.bf16.bf16.f32 "
        "{%0,%1,%2,%3},{%4,%5,%6,%7},{%8,%9},{%0,%1,%2,%3};"
        : "+f"(c[0]), "+f"(c[1]), "+f"(c[2]), "+f"(c[3])
        : "r"(a[0]), "r"(a[1]), "r"(a[2]), "r"(a[3]), "r"(b0), "r"(b1));
}

__device__ __forceinline__ void cp16(uint32_t dst, const void* src, bool valid) {
    int sz = valid ? 16 : 0;
    asm volatile("cp.async.ca.shared.global [%0], [%1], 16, %2;"
                 :: "r"(dst), "l"(src), "r"(sz));
}
__device__ __forceinline__ void cp_commit() {
    asm volatile("cp.async.commit_group;");
}
template <int NW>
__device__ __forceinline__ void cp_wait() {
    asm volatile("cp.async.wait_group %0;" :: "n"(NW));
}

// ---------------- split-BF16 GEMM, cp.async 3-stage pipeline ----------------
// BM=128, BN=128, BK=16. 256 threads = 8 warps; warp tile 64(M) x 32(N).
// One m16n8k16 covers the whole k-tile -> 48 MMAs/warp/k-tile (3-term split).
// A smem: As[row][24] fp32 (float2 frag loads even-bank distinct)
// B smem: Bs[k][132] fp32 k-major (scalar frag loads conflict-free)
constexpr int GBM = 128, GBN = 128, GBK = 16;
constexpr int APAD = 24;
constexpr int BSTR = 132;
constexpr int A_WORDS = GBM * APAD;            // 3072
constexpr int B_WORDS = GBK * BSTR;            // 2112
constexpr int STAGE_WORDS = A_WORDS + B_WORDS; // 5184
constexpr int NSTAGE = 3;
constexpr int GEMM_SMEM_BYTES = NSTAGE * STAGE_WORDS * 4;  // 62208

__device__ __forceinline__ void gemm_stage(float* stage,
                                           const float* A, const float* W,
                                           int N, int K, int M,
                                           int rowBase, int colBase, int k0, int tid) {
    float* As = stage;
    float* Bs = stage + A_WORDS;
    int c0   = tid * 2;
    int arow = c0 >> 2;
    int akq  = (c0 & 3) * 4;
    int grow = rowBase + arow;
    bool av  = grow < N;
    const float* asrc = &A[(size_t)grow * K + k0 + akq];
    uint32_t adst = (uint32_t)__cvta_generic_to_shared(&As[arow * APAD + akq]);
    cp16(adst, asrc, av);
    cp16(adst + 16, asrc + 4, av);
    int bk = tid >> 5;
    int bn = (tid & 31) * 4;
    const float* bsrc0 = &W[(size_t)(k0 + bk) * M + colBase + bn];
    const float* bsrc1 = &W[(size_t)(k0 + bk + 8) * M + colBase + bn];
    cp16((uint32_t)__cvta_generic_to_shared(&Bs[bk * BSTR + bn]), bsrc0, true);
    cp16((uint32_t)__cvta_generic_to_shared(&Bs[(bk + 8) * BSTR + bn]), bsrc1, true);
}

__device__ __forceinline__ void gemm_mma(const float* stage,
                                         float acc[4][4][4],
                                         int wr, int wc, int lq, int lr,
                                         const float* tS, const float* tT, int k0) {
    const float* As = stage;
    const float* Bs = stage + A_WORDS;
    int k2 = 2 * lr;        // this thread's k-pair base (0,2,4,6)

    // B fragments: b0 = k2,k2+1 ; b1 = k2+8,k2+9 at column n0
    uint32_t bh[4][2], bl[4][2];
#pragma unroll
    for (int nt = 0; nt < 4; nt++) {
        int n0 = wc * 32 + nt * 8 + lq;
        split_bf16x2(Bs[k2 * BSTR + n0],       Bs[(k2 + 1) * BSTR + n0],
                     bh[nt][0], bl[nt][0]);
        split_bf16x2(Bs[(k2 + 8) * BSTR + n0], Bs[(k2 + 9) * BSTR + n0],
                     bh[nt][1], bl[nt][1]);
    }

    float2 sA = make_float2(0.f, 0.f), tA = sA, sB = sA, tB = sA;
    bool tf = (tS != nullptr);
    if (tf) {
        sA = *(const float2*)&tS[k0 + k2];
        tA = *(const float2*)&tT[k0 + k2];
        sB = *(const float2*)&tS[k0 + k2 + 8];
        tB = *(const float2*)&tT[k0 + k2 + 8];
    }

#pragma unroll
    for (int mt = 0; mt < 4; mt++) {
        int r0 = wr * 64 + mt * 16 + lq;
        float2 p00 = *(const float2*)&As[r0 * APAD + k2];            // row r0, k2..k2+1
        float2 p10 = *(const float2*)&As[(r0 + 8) * APAD + k2];      // row r0+8
        float2 p01 = *(const float2*)&As[r0 * APAD + k2 + 8];        // row r0, k2+8..
        float2 p11 = *(const float2*)&As[(r0 + 8) * APAD + k2 + 8];
        if (tf) {
            p00.x = fmaxf(fmaf(p00.x, sA.x, tA.x), 0.f);
            p00.y = fmaxf(fmaf(p00.y, sA.y, tA.y), 0.f);
            p10.x = fmaxf(fmaf(p10.x, sA.x, tA.x), 0.f);
            p10.y = fmaxf(fmaf(p10.y, sA.y, tA.y), 0.f);
            p01.x = fmaxf(fmaf(p01.x, sB.x, tB.x), 0.f);
            p01.y = fmaxf(fmaf(p01.y, sB.y, tB.y), 0.f);
            p11.x = fmaxf(fmaf(p11.x, sB.x, tB.x), 0.f);
            p11.y = fmaxf(fmaf(p11.y, sB.y, tB.y), 0.f);
        }
        uint32_t ah[4], al[4];
        split_bf16x2(p00.x, p00.y, ah[0], al[0]);
        split_bf16x2(p10.x, p10.y, ah[1], al[1]);
        split_bf16x2(p01.x, p01.y, ah[2], al[2]);
        split_bf16x2(p11.x, p11.y, ah[3], al[3]);
#pragma unroll
        for (int nt = 0; nt < 4; nt++) {
            mma_bf16(acc[mt][nt], ah, bh[nt][0], bh[nt][1]);
            mma_bf16(acc[mt][nt], ah, bl[nt][0], bl[nt][1]);
            mma_bf16(acc[mt][nt], al, bh[nt][0], bh[nt][1]);
        }
    }
}

__device__ __forceinline__ void gemm_epilogue(float acc[4][4][4], const float* bias,
                                              const float* add, float* C, int N, int M,
                                              int rowBase, int colBase,
                                              int wr, int wc, int lq, int lr) {
#pragma unroll
    for (int mt = 0; mt < 4; mt++) {
#pragma unroll
        for (int nt = 0; nt < 4; nt++) {
            int c = colBase + wc * 32 + nt * 8 + 2 * lr;
            float2 bv = make_float2(0.f, 0.f);
            if (bias) bv = *(const float2*)&bias[c];
            int r0 = rowBase + wr * 64 + mt * 16 + lq;
            int r1 = r0 + 8;
            if (r0 < N) {
                float2 o = make_float2(acc[mt][nt][0] + bv.x, acc[mt][nt][1] + bv.y);
                if (add) {
                    float2 av = *(const float2*)&add[(size_t)r0 * M + c];
                    o.x += av.x; o.y += av.y;
                }
                *(float2*)&C[(size_t)r0 * M + c] = o;
            }
            if (r1 < N) {
                float2 o = make_float2(acc[mt][nt][2] + bv.x, acc[mt][nt][3] + bv.y);
                if (add) {
                    float2 av = *(const float2*)&add[(size_t)r1 * M + c];
                    o.x += av.x; o.y += av.y;
                }
                *(float2*)&C[(size_t)r1 * M + c] = o;
            }
        }
    }
}

// 3-stage mainloop: per iteration -> wait<1>, ONE sync, mma(t), stage(t+2), commit.
__device__ __forceinline__ void gemm_core(const float* A, const float* W,
                                          const float* bias, const float* add,
                                          const float* tS, const float* tT,
                                          float* C, int N, int K, int M,
                                          int rowBase, int colBase, float* sm) {
    int tid  = threadIdx.x;
    int lane = tid & 31;
    int w    = tid >> 5;
    int wr = w >> 2, wc = w & 3, lq = lane >> 2, lr = lane & 3;

    float acc[4][4][4];
#pragma unroll
    for (int mt = 0; mt < 4; mt++)
#pragma unroll
        for (int nt = 0; nt < 4; nt++)
#pragma unroll
            for (int i = 0; i < 4; i++) acc[mt][nt][i] = 0.f;

    int nk = K / GBK;
    gemm_stage(sm, A, W, N, K, M, rowBase, colBase, 0, tid);
    cp_commit();
    gemm_stage(sm + STAGE_WORDS, A, W, N, K, M, rowBase, colBase, GBK, tid);
    cp_commit();

    for (int t = 0; t < nk; t++) {
        cp_wait<1>();
        __syncthreads();
        gemm_mma(sm + (t % 3) * STAGE_WORDS, acc, wr, wc, lq, lr, tS, tT, t * GBK);
        if (t + 2 < nk)
            gemm_stage(sm + ((t + 2) % 3) * STAGE_WORDS, A, W, N, K, M,
                       rowBase, colBase, (t + 2) * GBK, tid);
        cp_commit();
    }
    __syncthreads();
    gemm_epilogue(acc, bias, add, C, N, M, rowBase, colBase, wr, wc, lq, lr);
}

// generic GEMM (W1; W2 with transform/add)
__global__ __launch_bounds__(256, 2)
void gemm_kernel(const float* __restrict__ A, const float* __restrict__ W,
                 const float* __restrict__ bias, const float* __restrict__ add,
                 const float* __restrict__ tS, const float* __restrict__ tT,
                 float* __restrict__ C, int N, int K, int M) {
    extern __shared__ float dynsm[];
    gemm_core(A, W, bias, add, tS, tT, C, N, K, M,
              blockIdx.x * GBM, blockIdx.y * GBN, dynsm);
}

// triple GEMM: shares A, computes xl/xr/xres. K=M=128. grid.y = 0..2 selects output.
__global__ __launch_bounds__(256, 2)
void gemm3_kernel(const float* __restrict__ A,
                  const float* __restrict__ W0, const float* __restrict__ W1,
                  const float* __restrict__ W2,
                  const float* __restrict__ b0, const float* __restrict__ b1,
                  const float* __restrict__ b2,
                  float* __restrict__ C0, float* __restrict__ C1,
                  float* __restrict__ C2) {
    extern __shared__ float dynsm[];
    int sel = blockIdx.y;
    const float* W    = (sel == 0) ? W0 : (sel == 1) ? W1 : W2;
    const float* bias = (sel == 0) ? b0 : (sel == 1) ? b1 : b2;
    float* C          = (sel == 0) ? C0 : (sel == 1) ? C1 : C2;
    gemm_core(A, W, bias, nullptr, nullptr, nullptr, C, NN, DD, DD,
              blockIdx.x * GBM, 0, dynsm);
}

// ---------------- fused edge kernel ----------------
__device__ __forceinline__ float lky(float v) { return v > 0.f ? v : NEG * v; }

__global__ __launch_bounds__(256)
void edge_fused_kernel(const int* __restrict__ ei, const float* __restrict__ ea,
                       const float* __restrict__ We, const float* __restrict__ att) {
    constexpr int TE = 128;
    constexpr int EW = 16;
    __shared__ float ea_s[TE * EDD];
    __shared__ float We_s[EDD * DD];
    __shared__ float att_s[DD];

    int tid  = threadIdx.x;
    int lane = tid & 31;
    int w    = tid >> 5;
    int e0   = blockIdx.x * TE;

    {
        const float4* We4 = (const float4*)We;
        float4* Ws4 = (float4*)We_s;
#pragma unroll
        for (int i = 0; i < 4; i++) Ws4[tid + 256 * i] = We4[tid + 256 * i];
        const float4* ea4 = (const float4*)(ea + (size_t)e0 * EDD);
        float4* es4 = (float4*)ea_s;
#pragma unroll
        for (int i = 0; i < 4; i++) es4[tid + 256 * i] = ea4[tid + 256 * i];
        if (tid < DD) att_s[tid] = att[tid];
    }
    __syncthreads();

    float acc[EW][4];
#pragma unroll
    for (int i = 0; i < EW; i++)
#pragma unroll
        for (int j = 0; j < 4; j++) acc[i][j] = 0.f;

#pragma unroll
    for (int k = 0; k < EDD; k++) {
        float4 wv = *(float4*)&We_s[k * DD + lane * 4];
#pragma unroll
        for (int i = 0; i < EW; i++) {
            float a = ea_s[(w * EW + i) * EDD + k];
            acc[i][0] = fmaf(a, wv.x, acc[i][0]);
            acc[i][1] = fmaf(a, wv.y, acc[i][1]);
            acc[i][2] = fmaf(a, wv.z, acc[i][2]);
            acc[i][3] = fmaf(a, wv.w, acc[i][3]);
        }
    }

    float4 attv = *(float4*)&att_s[lane * 4];

#pragma unroll 4
    for (int i = 0; i < EW; i++) {
        int e = e0 + w * EW + i;
        int s = ei[e];
        int d = ei[NE + e];
        float4 xlv = *(const float4*)&g_xl[(size_t)s * DD + lane * 4];
        float4 xrv = *(const float4*)&g_xr[(size_t)d * DD + lane * 4];
        float mx = lky(acc[i][0] + xlv.x + xrv.x);
        float my = lky(acc[i][1] + xlv.y + xrv.y);
        float mz = lky(acc[i][2] + xlv.z + xrv.z);
        float mw = lky(acc[i][3] + xlv.w + xrv.w);
        float p = mx * attv.x + my * attv.y + mz * attv.z + mw * attv.w;
        p += __shfl_xor_sync(0xffffffffu, p, 1);
        p += __shfl_xor_sync(0xffffffffu, p, 2);
        int pos = g_pos[e];
        if ((lane & 3) == 0) g_alpha[(size_t)pos * NH + (lane >> 2)] = p;
    }
}

// ---------------- node aggregation ----------------
__global__ __launch_bounds__(256)
void node_agg_kernel() {
    int lane = threadIdx.x & 31;
    int n = blockIdx.x * 8 + (threadIdx.x >> 5);
    if (n >= NN) return;
    int h = lane >> 2;
    int beg = g_rowptr[n], end = g_rowptr[n + 1];
    float m = NEG_INF, den = 0.f;
    float4 acc = make_float4(0.f, 0.f, 0.f, 0.f);

    int j = beg;
    for (; j + 1 < end; j += 2) {
        float a0 = g_alpha[(size_t)j * NH + h];
        float a1 = g_alpha[(size_t)(j + 1) * NH + h];
        int   s0 = g_src[j];
        int   s1 = g_src[j + 1];
        float4 x0 = *(const float4*)&g_xl[(size_t)s0 * DD + lane * 4];
        float4 x1 = *(const float4*)&g_xl[(size_t)s1 * DD + lane * 4];

        float mn = fmaxf(m, a0);
        float corr = __expf(m - mn);
        float p = __expf(a0 - mn);
        den = den * corr + p;
        acc.x = acc.x * corr + p * x0.x;
        acc.y = acc.y * corr + p * x0.y;
        acc.z = acc.z * corr + p * x0.z;
        acc.w = acc.w * corr + p * x0.w;
        m = mn;

        mn = fmaxf(m, a1);
        corr = __expf(m - mn);
        p = __expf(a1 - mn);
        den = den * corr + p;
        acc.x = acc.x * corr + p * x1.x;
        acc.y = acc.y * corr + p * x1.y;
        acc.z = acc.z * corr + p * x1.z;
        acc.w = acc.w * corr + p * x1.w;
        m = mn;
    }
    for (; j < end; j++) {
        float a = g_alpha[(size_t)j * NH + h];
        int s = g_src[j];
        float4 xlv = *(const float4*)&g_xl[(size_t)s * DD + lane * 4];
        float mn = fmaxf(m, a);
        float corr = __expf(m - mn);
        float p = __expf(a - mn);
        den = den * corr + p;
        acc.x = acc.x * corr + p * xlv.x;
        acc.y = acc.y * corr + p * xlv.y;
        acc.z = acc.z * corr + p * xlv.z;
        acc.w = acc.w * corr + p * xlv.w;
        m = mn;
    }

    float inv = 1.f / (den + 1e-16f);
    float4 rv = *(const float4*)&g_xres[(size_t)n * DD + lane * 4];
    float4 o = make_float4(acc.x * inv + rv.x, acc.y * inv + rv.y,
                           acc.z * inv + rv.z, acc.w * inv + rv.w);
    *(float4*)&g_xtmp[(size_t)n * DD + lane * 4] = o;
}

// ---------------- BN column stats ----------------
__global__ void colstats_kernel() {
    int col = blockIdx.x * 128 + threadIdx.x;
    constexpr int CHUNK = (NN + 63) / 64;
    int r0 = blockIdx.y * CHUNK;
    int r1 = min(r0 + CHUNK, NN);
    float s = 0.f, q = 0.f;
    for (int r = r0; r < r1; r++) {
        float v = g_h[(size_t)r * HD + col];
        s += v;
        q += v * v;
    }
    atomicAdd(&g_bnstat[col], s);
    atomicAdd(&g_bnstat[HD + col], q);
}

__global__ void bn_final_kernel(const float* __restrict__ gamma, const float* __restrict__ beta) {
    int c = threadIdx.x;
    if (c >= HD) return;
    float invn = 1.f / (float)NN;
    float mu  = g_bnstat[c] * invn;
    float var = g_bnstat[HD + c] * invn - mu * mu;
    float istd = rsqrtf(var + EPSC);
    float s = gamma[c] * istd;
    g_bns[c] = s;
    g_bnt[c] = beta[c] - mu * s;
}

// ---------------- graph LayerNorm ----------------
__global__ __launch_bounds__(256)
void ln_stats_kernel(const int* __restrict__ nb) {
    int lane = threadIdx.x & 31;
    int n = blockIdx.x * 8 + (threadIdx.x >> 5);
    if (n >= NN) return;
    float4 v = *(const float4*)&g_x2[(size_t)n * DD + lane * 4];
    float s = v.x + v.y + v.z + v.w;
    float q = v.x * v.x + v.y * v.y + v.z * v.z + v.w * v.w;
#pragma unroll
    for (int off = 16; off > 0; off >>= 1) {
        s += __shfl_xor_sync(0xffffffffu, s, off);
        q += __shfl_xor_sync(0xffffffffu, q, off);
    }
    if (lane == 0) {
        int g = nb[n];
        atomicAdd(&g_gstat[g], s);
        atomicAdd(&g_gstat[GG + g], q);
    }
}

__global__ void ln_final_kernel() {
    int g = threadIdx.x;
    if (g >= GG) return;
    float cnt = fmaxf((float)g_gcnt[g], 1.f);
    float denom = cnt * (float)DD;
    float mean = g_gstat[g] / denom;
    float var  = g_gstat[GG + g] / denom - mean * mean;
    g_gmean[g] = mean;
    g_ginv[g]  = rsqrtf(var + EPSC);
}

__global__ void ln_apply_kernel(const int* __restrict__ nb,
                                const float* __restrict__ gamma,
                                const float* __restrict__ beta,
                                float* __restrict__ dst) {
    int idx = blockIdx.x * blockDim.x + threadIdx.x;
    if (idx >= NN * (DD / 4)) return;
    int n  = idx >> 5;
    int c4 = (idx & 31) * 4;
    int g  = nb[n];
    float mean = g_gmean[g];
    float ginv = g_ginv[g];
    float4 v  = *(const float4*)&g_x2[(size_t)n * DD + c4];
    float4 ga = *(const float4*)&gamma[c4];
    float4 be = *(const float4*)&beta[c4];
    float4 o;
    o.x = (v.x - mean) * ginv * ga.x + be.x;
    o.y = (v.y - mean) * ginv * ga.y + be.y;
    o.z = (v.z - mean) * ginv * ga.z + be.z;
    o.w = (v.w - mean) * ginv * ga.w + be.w;
    *(float4*)&dst[(size_t)n * DD + c4] = o;
}

// ---------------- host launch ----------------
extern "C" void kernel_launch(void* const* d_in, const int* in_sizes, int n_in,
                              void* d_out, int out_size) {
    const float* x    = (const float*)d_in[0];
    const int*   nb   = (const int*)  d_in[1];
    const int*   ei   = (const int*)  d_in[2];
    const float* ea   = (const float*)d_in[3];
    const float* Wl   = (const float*)d_in[4];
    const float* bl   = (const float*)d_in[5];
    const float* Wr   = (const float*)d_in[6];
    const float* br   = (const float*)d_in[7];
    const float* We   = (const float*)d_in[8];
    const float* att  = (const float*)d_in[9];
    const float* bias = (const float*)d_in[10];
    const float* Wres = (const float*)d_in[11];
    const float* W1   = (const float*)d_in[12];
    const float* b1   = (const float*)d_in[13];
    const float* bng  = (const float*)d_in[14];
    const float* bnb  = (const float*)d_in[15];
    const float* W2   = (const float*)d_in[16];
    const float* b2   = (const float*)d_in[17];
    const float* lng  = (const float*)d_in[18];
    const float* lnb  = (const float*)d_in[19];
    float* out = (float*)d_out;

    void* p;
    cudaGetSymbolAddress(&p, g_xl);   float* pxl   = (float*)p;
    cudaGetSymbolAddress(&p, g_xr);   float* pxr   = (float*)p;
    cudaGetSymbolAddress(&p, g_xres); float* pxres = (float*)p;
    cudaGetSymbolAddress(&p, g_xtmp); float* pxtmp = (float*)p;
    cudaGetSymbolAddress(&p, g_x2);   float* px2   = (float*)p;
    cudaGetSymbolAddress(&p, g_xcur); float* pxcur = (float*)p;
    cudaGetSymbolAddress(&p, g_h);    float* ph    = (float*)p;
    cudaGetSymbolAddress(&p, g_bns);  float* pbns  = (float*)p;
    cudaGetSymbolAddress(&p, g_bnt);  float* pbnt  = (float*)p;

    cudaFuncSetAttribute(gemm_kernel,  cudaFuncAttributeMaxDynamicSharedMemorySize, GEMM_SMEM_BYTES);
    cudaFuncSetAttribute(gemm3_kernel, cudaFuncAttributeMaxDynamicSharedMemorySize, GEMM_SMEM_BYTES);

    const int GR = (NN + 127) / 128;   // 391

    // launches 1-3 (CSR prologue); layer-0 gemm3 is launch #4 for the ncu window
    zero_init_kernel<<<(NN + 255) / 256, 256>>>();
    hist_kernel<<<(NE + 255) / 256, 256>>>(ei, nb);
    scan_kernel<<<1, 1024>>>();

    const float* xin = x;
    for (int l = 0; l < 2; l++) {
        gemm3_kernel<<<dim3(GR, 3), 256, GEMM_SMEM_BYTES>>>(xin,
            Wl + (size_t)l * DD * DD, Wr + (size_t)l * DD * DD, Wres + (size_t)l * DD * DD,
            bl + l * DD, br + l * DD, bias + l * DD,
            pxl, pxr, pxres);
        if (l == 0) scatter_kernel<<<(NE + 255) / 256, 256>>>(ei);
        zero_stats_kernel<<<2, 1024>>>();

        edge_fused_kernel<<<NE / 128, 256>>>(ei, ea, We + (size_t)l * EDD * DD, att + l * DD);
        node_agg_kernel<<<(NN + 7) / 8, 256>>>();

        gemm_kernel<<<dim3(GR, 4), 256, GEMM_SMEM_BYTES>>>(pxtmp, W1 + (size_t)l * DD * HD, b1 + l * HD,
                                          nullptr, nullptr, nullptr, ph, NN, DD, HD);
        colstats_kernel<<<dim3(4, 64), 128>>>();
        bn_final_kernel<<<1, 512>>>(bng + l * HD, bnb + l * HD);
        gemm_kernel<<<dim3(GR, 1), 256, GEMM_SMEM_BYTES>>>(ph, W2 + (size_t)l * HD * DD, b2 + l * DD,
                                          pxtmp, pbns, pbnt, px2, NN, HD, DD);

        ln_stats_kernel<<<(NN + 7) / 8, 256>>>(nb);
        ln_final_kernel<<<1, 64>>>();
        float* dst = (l == 1) ? out : pxcur;
        ln_apply_kernel<<<(NN * (DD / 4) + 255) / 256, 256>>>(nb, lng + l * DD, lnb + l * DD, dst);

        xin = pxcur;
    }
}

// round 13
// speedup vs baseline: 1.8127x; 1.3588x over previous
#include <cuda_runtime.h>
#include <cuda_bf16.h>
#include <cstdint>
#include <cstdio>

// ---------------- problem constants ----------------
constexpr int NN  = 50000;   // nodes
constexpr int NE  = 800000;  // edges
constexpr int DD  = 128;     // channels
constexpr int NH  = 8;       // heads
constexpr int EDD = 32;      // edge_dim
constexpr int HD  = 512;     // mlp hidden
constexpr int GG  = 64;      // graphs
constexpr float NEG  = 0.2f;
constexpr float EPSC = 1e-5f;

#define NEG_INF (__int_as_float(0xff800000u))

// ---------------- device scratch ----------------
__device__ float g_xl  [NN * DD];
__device__ float g_xr  [NN * DD];
__device__ float g_xres[NN * DD];
__device__ float g_xtmp[NN * DD];
__device__ float g_x2  [NN * DD];
__device__ float g_xcur[NN * DD];
__device__ float g_h   [(size_t)NN * HD];

__device__ int g_deg   [NN];
__device__ int g_rowptr[NN + 1];
__device__ int g_wp    [NN];
__device__ int g_eid   [NE];   // CSR position -> edge id
__device__ int g_src   [NE];   // CSR position -> src node
__device__ int g_gcnt  [GG];

__device__ float g_bnstat[2 * HD];
__device__ float g_bns[HD];
__device__ float g_bnt[HD];
__device__ float g_gstat[2 * GG];
__device__ float g_gmean[GG];
__device__ float g_ginv [GG];

// ---------------- setup kernels ----------------
__global__ void zero_init_kernel() {
    int i = blockIdx.x * blockDim.x + threadIdx.x;
    if (i < NN) g_deg[i] = 0;
    if (i < GG) g_gcnt[i] = 0;
}

__global__ void hist_kernel(const int* __restrict__ ei, const int* __restrict__ nb) {
    int i = blockIdx.x * blockDim.x + threadIdx.x;
    if (i < NE) atomicAdd(&g_deg[ei[NE + i]], 1);
    if (i < NN) atomicAdd(&g_gcnt[nb[i]], 1);
}

__global__ void scan_kernel() {
    __shared__ int part[1024];
    constexpr int CHUNK = (NN + 1023) / 1024;
    int t = threadIdx.x;
    int base = t * CHUNK;
    int s = 0;
    for (int i = 0; i < CHUNK; i++) {
        int idx = base + i;
        if (idx < NN) s += g_deg[idx];
    }
    part[t] = s;
    __syncthreads();
    for (int off = 1; off < 1024; off <<= 1) {
        int v = (t >= off) ? part[t - off] : 0;
        __syncthreads();
        part[t] += v;
        __syncthreads();
    }
    int run = (t == 0) ? 0 : part[t - 1];
    for (int i = 0; i < CHUNK; i++) {
        int idx = base + i;
        if (idx < NN) {
            g_rowptr[idx] = run;
            g_wp[idx] = run;
            run += g_deg[idx];
        }
    }
    if (t == 1023) g_rowptr[NN] = part[1023];
}

__global__ void scatter_kernel(const int* __restrict__ ei) {
    int e = blockIdx.x * blockDim.x + threadIdx.x;
    if (e >= NE) return;
    int s = ei[e];
    int d = ei[NE + e];
    int p = atomicAdd(&g_wp[d], 1);
    g_eid[p] = e;
    g_src[p] = s;
}

__global__ void zero_stats_kernel() {
    int i = blockIdx.x * blockDim.x + threadIdx.x;
    if (i < 2 * HD) g_bnstat[i] = 0.f;
    if (i < 2 * GG) g_gstat[i] = 0.f;
}

// ---------------- split-BF16 + cp.async helpers ----------------
__device__ __forceinline__ void split_bf16x2(float f0, float f1,
                                             uint32_t& hi, uint32_t& lo) {
    __nv_bfloat162 h = __floats2bfloat162_rn(f0, f1);
    float r0 = f0 - __bfloat162float(h.x);
    float r1 = f1 - __bfloat162float(h.y);
    __nv_bfloat162 l = __floats2bfloat162_rn(r0, r1);
    hi = *(uint32_t*)&h;
    lo = *(uint32_t*)&l;
}

__device__ __forceinline__ void mma_bf16(float c[4], const uint32_t a[4],
                                         uint32_t b0, uint32_t b1) {
    asm volatile(
        "mma.sync.aligned.m16n8k16.row.col.f32.bf16.bf16.f32 "
        "{%0,%1,%2,%3},{%4,%5,%6,%7},{%8,%9},{%0,%1,%2,%3};"
        : "+f"(c[0]), "+f"(c[1]), "+f"(c[2]), "+f"(c[3])
        : "r"(a[0]), "r"(a[1]), "r"(a[2]), "r"(a[3]), "r"(b0), "r"(b1));
}

__device__ __forceinline__ void cp16(uint32_t dst, const void* src, bool valid) {
    int sz = valid ? 16 : 0;
    asm volatile("cp.async.ca.shared.global [%0], [%1], 16, %2;"
                 :: "r"(dst), "l"(src), "r"(sz));
}
__device__ __forceinline__ void cp_commit() {
    asm volatile("cp.async.commit_group;");
}
template <int NW>
__device__ __forceinline__ void cp_wait() {
    asm volatile("cp.async.wait_group %0;" :: "n"(NW));
}

// ---------------- split-BF16 GEMM, cp.async 3-stage pipeline ----------------
constexpr int GBM = 128, GBN = 128, GBK = 16;
constexpr int APAD = 24;
constexpr int BSTR = 132;
constexpr int A_WORDS = GBM * APAD;            // 3072
constexpr int B_WORDS = GBK * BSTR;            // 2112
constexpr int STAGE_WORDS = A_WORDS + B_WORDS; // 5184
constexpr int NSTAGE = 3;
constexpr int GEMM_SMEM_BYTES = NSTAGE * STAGE_WORDS * 4;  // 62208

__device__ __forceinline__ void gemm_stage(float* stage,
                                           const float* A, const float* W,
                                           int N, int K, int M,
                                           int rowBase, int colBase, int k0, int tid) {
    float* As = stage;
    float* Bs = stage + A_WORDS;
    int c0   = tid * 2;
    int arow = c0 >> 2;
    int akq  = (c0 & 3) * 4;
    int grow = rowBase + arow;
    bool av  = grow < N;
    const float* asrc = &A[(size_t)grow * K + k0 + akq];
    uint32_t adst = (uint32_t)__cvta_generic_to_shared(&As[arow * APAD + akq]);
    cp16(adst, asrc, av);
    cp16(adst + 16, asrc + 4, av);
    int bk = tid >> 5;
    int bn = (tid & 31) * 4;
    const float* bsrc0 = &W[(size_t)(k0 + bk) * M + colBase + bn];
    const float* bsrc1 = &W[(size_t)(k0 + bk + 8) * M + colBase + bn];
    cp16((uint32_t)__cvta_generic_to_shared(&Bs[bk * BSTR + bn]), bsrc0, true);
    cp16((uint32_t)__cvta_generic_to_shared(&Bs[(bk + 8) * BSTR + bn]), bsrc1, true);
}

__device__ __forceinline__ void gemm_mma(const float* stage,
                                         float acc[4][4][4],
                                         int wr, int wc, int lq, int lr,
                                         const float* tS, const float* tT, int k0) {
    const float* As = stage;
    const float* Bs = stage + A_WORDS;
    int k2 = 2 * lr;

    uint32_t bh[4][2], bl[4][2];
#pragma unroll
    for (int nt = 0; nt < 4; nt++) {
        int n0 = wc * 32 + nt * 8 + lq;
        split_bf16x2(Bs[k2 * BSTR + n0],       Bs[(k2 + 1) * BSTR + n0],
                     bh[nt][0], bl[nt][0]);
        split_bf16x2(Bs[(k2 + 8) * BSTR + n0], Bs[(k2 + 9) * BSTR + n0],
                     bh[nt][1], bl[nt][1]);
    }

    float2 sA = make_float2(0.f, 0.f), tA = sA, sB = sA, tB = sA;
    bool tf = (tS != nullptr);
    if (tf) {
        sA = *(const float2*)&tS[k0 + k2];
        tA = *(const float2*)&tT[k0 + k2];
        sB = *(const float2*)&tS[k0 + k2 + 8];
        tB = *(const float2*)&tT[k0 + k2 + 8];
    }

#pragma unroll
    for (int mt = 0; mt < 4; mt++) {
        int r0 = wr * 64 + mt * 16 + lq;
        float2 p00 = *(const float2*)&As[r0 * APAD + k2];
        float2 p10 = *(const float2*)&As[(r0 + 8) * APAD + k2];
        float2 p01 = *(const float2*)&As[r0 * APAD + k2 + 8];
        float2 p11 = *(const float2*)&As[(r0 + 8) * APAD + k2 + 8];
        if (tf) {
            p00.x = fmaxf(fmaf(p00.x, sA.x, tA.x), 0.f);
            p00.y = fmaxf(fmaf(p00.y, sA.y, tA.y), 0.f);
            p10.x = fmaxf(fmaf(p10.x, sA.x, tA.x), 0.f);
            p10.y = fmaxf(fmaf(p10.y, sA.y, tA.y), 0.f);
            p01.x = fmaxf(fmaf(p01.x, sB.x, tB.x), 0.f);
            p01.y = fmaxf(fmaf(p01.y, sB.y, tB.y), 0.f);
            p11.x = fmaxf(fmaf(p11.x, sB.x, tB.x), 0.f);
            p11.y = fmaxf(fmaf(p11.y, sB.y, tB.y), 0.f);
        }
        uint32_t ah[4], al[4];
        split_bf16x2(p00.x, p00.y, ah[0], al[0]);
        split_bf16x2(p10.x, p10.y, ah[1], al[1]);
        split_bf16x2(p01.x, p01.y, ah[2], al[2]);
        split_bf16x2(p11.x, p11.y, ah[3], al[3]);
#pragma unroll
        for (int nt = 0; nt < 4; nt++) {
            mma_bf16(acc[mt][nt], ah, bh[nt][0], bh[nt][1]);
            mma_bf16(acc[mt][nt], ah, bl[nt][0], bl[nt][1]);
            mma_bf16(acc[mt][nt], al, bh[nt][0], bh[nt][1]);
        }
    }
}

__device__ __forceinline__ void gemm_epilogue(float acc[4][4][4], const float* bias,
                                              const float* add, float* C, int N, int M,
                                              int rowBase, int colBase,
                                              int wr, int wc, int lq, int lr) {
#pragma unroll
    for (int mt = 0; mt < 4; mt++) {
#pragma unroll
        for (int nt = 0; nt < 4; nt++) {
            int c = colBase + wc * 32 + nt * 8 + 2 * lr;
            float2 bv = make_float2(0.f, 0.f);
            if (bias) bv = *(const float2*)&bias[c];
            int r0 = rowBase + wr * 64 + mt * 16 + lq;
            int r1 = r0 + 8;
            if (r0 < N) {
                float2 o = make_float2(acc[mt][nt][0] + bv.x, acc[mt][nt][1] + bv.y);
                if (add) {
                    float2 av = *(const float2*)&add[(size_t)r0 * M + c];
                    o.x += av.x; o.y += av.y;
                }
                *(float2*)&C[(size_t)r0 * M + c] = o;
            }
            if (r1 < N) {
                float2 o = make_float2(acc[mt][nt][2] + bv.x, acc[mt][nt][3] + bv.y);
                if (add) {
                    float2 av = *(const float2*)&add[(size_t)r1 * M + c];
                    o.x += av.x; o.y += av.y;
                }
                *(float2*)&C[(size_t)r1 * M + c] = o;
            }
        }
    }
}

__device__ __forceinline__ void gemm_core(const float* A, const float* W,
                                          const float* bias, const float* add,
                                          const float* tS, const float* tT,
                                          float* C, int N, int K, int M,
                                          int rowBase, int colBase, float* sm) {
    int tid  = threadIdx.x;
    int lane = tid & 31;
    int w    = tid >> 5;
    int wr = w >> 2, wc = w & 3, lq = lane >> 2, lr = lane & 3;

    float acc[4][4][4];
#pragma unroll
    for (int mt = 0; mt < 4; mt++)
#pragma unroll
        for (int nt = 0; nt < 4; nt++)
#pragma unroll
            for (int i = 0; i < 4; i++) acc[mt][nt][i] = 0.f;

    int nk = K / GBK;
    gemm_stage(sm, A, W, N, K, M, rowBase, colBase, 0, tid);
    cp_commit();
    gemm_stage(sm + STAGE_WORDS, A, W, N, K, M, rowBase, colBase, GBK, tid);
    cp_commit();

    for (int t = 0; t < nk; t++) {
        cp_wait<1>();
        __syncthreads();
        gemm_mma(sm + (t % 3) * STAGE_WORDS, acc, wr, wc, lq, lr, tS, tT, t * GBK);
        if (t + 2 < nk)
            gemm_stage(sm + ((t + 2) % 3) * STAGE_WORDS, A, W, N, K, M,
                       rowBase, colBase, (t + 2) * GBK, tid);
        cp_commit();
    }
    __syncthreads();
    gemm_epilogue(acc, bias, add, C, N, M, rowBase, colBase, wr, wc, lq, lr);
}

__global__ __launch_bounds__(256, 2)
void gemm_kernel(const float* __restrict__ A, const float* __restrict__ W,
                 const float* __restrict__ bias, const float* __restrict__ add,
                 const float* __restrict__ tS, const float* __restrict__ tT,
                 float* __restrict__ C, int N, int K, int M) {
    extern __shared__ float dynsm[];
    gemm_core(A, W, bias, add, tS, tT, C, N, K, M,
              blockIdx.x * GBM, blockIdx.y * GBN, dynsm);
}

__global__ __launch_bounds__(256, 2)
void gemm3_kernel(const float* __restrict__ A,
                  const float* __restrict__ W0, const float* __restrict__ W1,
                  const float* __restrict__ W2,
                  const float* __restrict__ b0, const float* __restrict__ b1,
                  const float* __restrict__ b2,
                  float* __restrict__ C0, float* __restrict__ C1,
                  float* __restrict__ C2) {
    extern __shared__ float dynsm[];
    int sel = blockIdx.y;
    const float* W    = (sel == 0) ? W0 : (sel == 1) ? W1 : W2;
    const float* bias = (sel == 0) ? b0 : (sel == 1) ? b1 : b2;
    float* C          = (sel == 0) ? C0 : (sel == 1) ? C1 : C2;
    gemm_core(A, W, bias, nullptr, nullptr, nullptr, C, NN, DD, DD,
              blockIdx.x * GBM, 0, dynsm);
}

// ---------------- fused edge+aggregation kernel (CSR order) ----------------
// One warp per node. For each incoming edge group (4 edges):
//   - gather ea rows (1 float/lane) + xl[src] (float4/lane)
//   - in-warp projection: k-loop shares one We_s float4 LDS across the 4 edges
//   - leaky + att dot + quad shfl-reduce -> alpha
//   - online-softmax update reusing the xl registers
// xr[dst] loaded ONCE per node; alpha never touches DRAM.
__device__ __forceinline__ float lky(float v) { return v > 0.f ? v : NEG * v; }
constexpr int GRP = 4;

__global__ __launch_bounds__(256)
void node_fused_kernel(const float* __restrict__ ea, const float* __restrict__ We,
                       const float* __restrict__ att) {
    __shared__ float We_s[EDD * DD];   // [k][c], 16 KB
    __shared__ float att_s[DD];

    int tid  = threadIdx.x;
    int lane = tid & 31;
    int w    = tid >> 5;

    {
        const float4* We4 = (const float4*)We;
        float4* Ws4 = (float4*)We_s;
#pragma unroll
        for (int i = 0; i < 4; i++) Ws4[tid + 256 * i] = We4[tid + 256 * i];
        if (tid < DD) att_s[tid] = att[tid];
    }
    __syncthreads();

    int n = blockIdx.x * 8 + w;
    if (n >= NN) return;

    float4 attv = *(float4*)&att_s[lane * 4];
    float4 xrv  = *(const float4*)&g_xr[(size_t)n * DD + lane * 4];
    int beg = g_rowptr[n], end = g_rowptr[n + 1];

    float m = NEG_INF, den = 0.f;
    float4 acc = make_float4(0.f, 0.f, 0.f, 0.f);

    for (int j = beg; j < end; j += GRP) {
        int cnt = min(end - j, GRP);
        float  av[GRP];
        float4 xlv[GRP];
#pragma unroll
        for (int g = 0; g < GRP; g++) {
            int jj = (j + g < end) ? (j + g) : j;   // clamp: keeps loads in-bounds
            int e = g_eid[jj];
            int s = g_src[jj];
            av[g]  = ea[(size_t)e * EDD + lane];
            xlv[g] = *(const float4*)&g_xl[(size_t)s * DD + lane * 4];
        }

        float4 pr[GRP];
#pragma unroll
        for (int g = 0; g < GRP; g++) pr[g] = make_float4(0.f, 0.f, 0.f, 0.f);

#pragma unroll
        for (int k = 0; k < EDD; k++) {
            float4 wv = *(float4*)&We_s[k * DD + lane * 4];
#pragma unroll
            for (int g = 0; g < GRP; g++) {
                float a = __shfl_sync(0xffffffffu, av[g], k);
                pr[g].x = fmaf(a, wv.x, pr[g].x);
                pr[g].y = fmaf(a, wv.y, pr[g].y);
                pr[g].z = fmaf(a, wv.z, pr[g].z);
                pr[g].w = fmaf(a, wv.w, pr[g].w);
            }
        }

#pragma unroll
        for (int g = 0; g < GRP; g++) {
            if (g >= cnt) break;   // cnt warp-uniform
            float mx = lky(pr[g].x + xlv[g].x + xrv.x);
            float my = lky(pr[g].y + xlv[g].y + xrv.y);
            float mz = lky(pr[g].z + xlv[g].z + xrv.z);
            float mw = lky(pr[g].w + xlv[g].w + xrv.w);
            float p = mx * attv.x + my * attv.y + mz * attv.z + mw * attv.w;
            p += __shfl_xor_sync(0xffffffffu, p, 1);
            p += __shfl_xor_sync(0xffffffffu, p, 2);   // all 4 lanes of head hold alpha
            float mn = fmaxf(m, p);
            float corr = __expf(m - mn);
            float pe = __expf(p - mn);
            den = den * corr + pe;
            acc.x = acc.x * corr + pe * xlv[g].x;
            acc.y = acc.y * corr + pe * xlv[g].y;
            acc.z = acc.z * corr + pe * xlv[g].z;
            acc.w = acc.w * corr + pe * xlv[g].w;
            m = mn;
        }
    }

    float inv = 1.f / (den + 1e-16f);
    float4 rv = *(const float4*)&g_xres[(size_t)n * DD + lane * 4];
    float4 o = make_float4(acc.x * inv + rv.x, acc.y * inv + rv.y,
                           acc.z * inv + rv.z, acc.w * inv + rv.w);
    *(float4*)&g_xtmp[(size_t)n * DD + lane * 4] = o;
}

// ---------------- BN column stats ----------------
__global__ void colstats_kernel() {
    int col = blockIdx.x * 128 + threadIdx.x;
    constexpr int CHUNK = (NN + 63) / 64;
    int r0 = blockIdx.y * CHUNK;
    int r1 = min(r0 + CHUNK, NN);
    float s = 0.f, q = 0.f;
    for (int r = r0; r < r1; r++) {
        float v = g_h[(size_t)r * HD + col];
        s += v;
        q += v * v;
    }
    atomicAdd(&g_bnstat[col], s);
    atomicAdd(&g_bnstat[HD + col], q);
}

__global__ void bn_final_kernel(const float* __restrict__ gamma, const float* __restrict__ beta) {
    int c = threadIdx.x;
    if (c >= HD) return;
    float invn = 1.f / (float)NN;
    float mu  = g_bnstat[c] * invn;
    float var = g_bnstat[HD + c] * invn - mu * mu;
    float istd = rsqrtf(var + EPSC);
    float s = gamma[c] * istd;
    g_bns[c] = s;
    g_bnt[c] = beta[c] - mu * s;
}

// ---------------- graph LayerNorm ----------------
__global__ __launch_bounds__(256)
void ln_stats_kernel(const int* __restrict__ nb) {
    int lane = threadIdx.x & 31;
    int n = blockIdx.x * 8 + (threadIdx.x >> 5);
    if (n >= NN) return;
    float4 v = *(const float4*)&g_x2[(size_t)n * DD + lane * 4];
    float s = v.x + v.y + v.z + v.w;
    float q = v.x * v.x + v.y * v.y + v.z * v.z + v.w * v.w;
#pragma unroll
    for (int off = 16; off > 0; off >>= 1) {
        s += __shfl_xor_sync(0xffffffffu, s, off);
        q += __shfl_xor_sync(0xffffffffu, q, off);
    }
    if (lane == 0) {
        int g = nb[n];
        atomicAdd(&g_gstat[g], s);
        atomicAdd(&g_gstat[GG + g], q);
    }
}

__global__ void ln_final_kernel() {
    int g = threadIdx.x;
    if (g >= GG) return;
    float cnt = fmaxf((float)g_gcnt[g], 1.f);
    float denom = cnt * (float)DD;
    float mean = g_gstat[g] / denom;
    float var  = g_gstat[GG + g] / denom - mean * mean;
    g_gmean[g] = mean;
    g_ginv[g]  = rsqrtf(var + EPSC);
}

__global__ void ln_apply_kernel(const int* __restrict__ nb,
                                const float* __restrict__ gamma,
                                const float* __restrict__ beta,
                                float* __restrict__ dst) {
    int idx = blockIdx.x * blockDim.x + threadIdx.x;
    if (idx >= NN * (DD / 4)) return;
    int n  = idx >> 5;
    int c4 = (idx & 31) * 4;
    int g  = nb[n];
    float mean = g_gmean[g];
    float ginv = g_ginv[g];
    float4 v  = *(const float4*)&g_x2[(size_t)n * DD + c4];
    float4 ga = *(const float4*)&gamma[c4];
    float4 be = *(const float4*)&beta[c4];
    float4 o;
    o.x = (v.x - mean) * ginv * ga.x + be.x;
    o.y = (v.y - mean) * ginv * ga.y + be.y;
    o.z = (v.z - mean) * ginv * ga.z + be.z;
    o.w = (v.w - mean) * ginv * ga.w + be.w;
    *(float4*)&dst[(size_t)n * DD + c4] = o;
}

// ---------------- host launch ----------------
extern "C" void kernel_launch(void* const* d_in, const int* in_sizes, int n_in,
                              void* d_out, int out_size) {
    const float* x    = (const float*)d_in[0];
    const int*   nb   = (const int*)  d_in[1];
    const int*   ei   = (const int*)  d_in[2];
    const float* ea   = (const float*)d_in[3];
    const float* Wl   = (const float*)d_in[4];
    const float* bl   = (const float*)d_in[5];
    const float* Wr   = (const float*)d_in[6];
    const float* br   = (const float*)d_in[7];
    const float* We   = (const float*)d_in[8];
    const float* att  = (const float*)d_in[9];
    const float* bias = (const float*)d_in[10];
    const float* Wres = (const float*)d_in[11];
    const float* W1   = (const float*)d_in[12];
    const float* b1   = (const float*)d_in[13];
    const float* bng  = (const float*)d_in[14];
    const float* bnb  = (const float*)d_in[15];
    const float* W2   = (const float*)d_in[16];
    const float* b2   = (const float*)d_in[17];
    const float* lng  = (const float*)d_in[18];
    const float* lnb  = (const float*)d_in[19];
    float* out = (float*)d_out;

    void* p;
    cudaGetSymbolAddress(&p, g_xl);   float* pxl   = (float*)p;
    cudaGetSymbolAddress(&p, g_xr);   float* pxr   = (float*)p;
    cudaGetSymbolAddress(&p, g_xres); float* pxres = (float*)p;
    cudaGetSymbolAddress(&p, g_xtmp); float* pxtmp = (float*)p;
    cudaGetSymbolAddress(&p, g_x2);   float* px2   = (float*)p;
    cudaGetSymbolAddress(&p, g_xcur); float* pxcur = (float*)p;
    cudaGetSymbolAddress(&p, g_h);    float* ph    = (float*)p;
    cudaGetSymbolAddress(&p, g_bns);  float* pbns  = (float*)p;
    cudaGetSymbolAddress(&p, g_bnt);  float* pbnt  = (float*)p;

    cudaFuncSetAttribute(gemm_kernel,  cudaFuncAttributeMaxDynamicSharedMemorySize, GEMM_SMEM_BYTES);
    cudaFuncSetAttribute(gemm3_kernel, cudaFuncAttributeMaxDynamicSharedMemorySize, GEMM_SMEM_BYTES);

    const int GR = (NN + 127) / 128;   // 391

    // launches 1-3 (CSR prologue); layer-0 gemm3 is launch #4 for the ncu window
    zero_init_kernel<<<(NN + 255) / 256, 256>>>();
    hist_kernel<<<(NE + 255) / 256, 256>>>(ei, nb);
    scan_kernel<<<1, 1024>>>();

    const float* xin = x;
    for (int l = 0; l < 2; l++) {
        gemm3_kernel<<<dim3(GR, 3), 256, GEMM_SMEM_BYTES>>>(xin,
            Wl + (size_t)l * DD * DD, Wr + (size_t)l * DD * DD, Wres + (size_t)l * DD * DD,
            bl + l * DD, br + l * DD, bias + l * DD,
            pxl, pxr, pxres);
        if (l == 0) scatter_kernel<<<(NE + 255) / 256, 256>>>(ei);
        zero_stats_kernel<<<2, 1024>>>();

        node_fused_kernel<<<(NN + 7) / 8, 256>>>(ea, We + (size_t)l * EDD * DD, att + l * DD);

        gemm_kernel<<<dim3(GR, 4), 256, GEMM_SMEM_BYTES>>>(pxtmp, W1 + (size_t)l * DD * HD, b1 + l * HD,
                                          nullptr, nullptr, nullptr, ph, NN, DD, HD);
        colstats_kernel<<<dim3(4, 64), 128>>>();
        bn_final_kernel<<<1, 512>>>(bng + l * HD, bnb + l * HD);
        gemm_kernel<<<dim3(GR, 1), 256, GEMM_SMEM_BYTES>>>(ph, W2 + (size_t)l * HD * DD, b2 + l * DD,
                                          pxtmp, pbns, pbnt, px2, NN, HD, DD);

        ln_stats_kernel<<<(NN + 7) / 8, 256>>>(nb);
        ln_final_kernel<<<1, 64>>>();
        float* dst = (l == 1) ? out : pxcur;
        ln_apply_kernel<<<(NN * (DD / 4) + 255) / 256, 256>>>(nb, lng + l * DD, lnb + l * DD, dst);

        xin = pxcur;
    }
}